// round 1
// baseline (speedup 1.0000x reference)
#include <cuda_runtime.h>
#include <math.h>

#define B_   2
#define C_   256
#define H_   100
#define W_   152
#define HW_  (H_*W_)
#define P_   2
#define KB_  5          // bins
#define DEXP (P_*C_)    // 512

// ---------------- scratch (static device memory; no allocation) -------------
__device__ float g_ef   [(size_t)B_*HW_*DEXP];   // (B, HW, 512) pixel-major expand feat
__device__ float g_buf2 [(size_t)B_*HW_*DEXP];   // h: (B*P, HW, 256) then outs: (B, HW, 512)
__device__ float g_heat [B_*P_*HW_];             // (B*P, HW)
__device__ float g_merged[(size_t)B_*C_*HW_];    // (B, C, HW) channel-major
__device__ float g_stat [B_*32*2];               // (b,g) -> mu, rstd

// ---------------- generic tiled SGEMM ---------------------------------------
// C[M,N] = A * B (+bias) (+relu).
// TA: A stored row-major [K][M] (i.e. logically transposed), else [M][K].
// TB: B stored row-major [N][K] (transposed), else [K][N].
// z = blockIdx.z decomposed as z1 = z/zdiv, z2 = z%zdiv for batch/point strides.
#define BM 128
#define BN 64
#define BK 16
#define TM 8
#define TN 4

template<bool TA, bool TB, int BIAS, bool RELU>
__global__ __launch_bounds__(256)
void sgemm(const float* __restrict__ A, int lda, long sA1, long sA2,
           const float* __restrict__ Bm, int ldb, long sB1, long sB2,
           float* __restrict__ Cm, int ldc, long sC1, long sC2,
           const float* __restrict__ bias, long sb1, long sb2,
           int zdiv, int M, int N, int K)
{
    __shared__ float As[BK][BM + 4];
    __shared__ float Bs[BK][BN + 4];

    int z  = blockIdx.z;
    int z1 = z / zdiv, z2 = z % zdiv;
    A  += z1 * sA1 + z2 * sA2;
    Bm += z1 * sB1 + z2 * sB2;
    Cm += z1 * sC1 + z2 * sC2;
    const float* bptr = bias ? (bias + z1 * sb1 + z2 * sb2) : nullptr;

    const int m0 = blockIdx.y * BM;
    const int n0 = blockIdx.x * BN;
    const int tid = threadIdx.x;
    const int tx = tid & 15, ty = tid >> 4;

    float acc[TM][TN];
#pragma unroll
    for (int i = 0; i < TM; i++)
#pragma unroll
        for (int j = 0; j < TN; j++) acc[i][j] = 0.f;

    for (int k0 = 0; k0 < K; k0 += BK) {
        // ---- load A tile ----
        if (TA) {
#pragma unroll
            for (int t = tid; t < BK * BM; t += 256) {
                int k = t / BM, m = t % BM;
                int gm = m0 + m;
                As[k][m] = (gm < M) ? A[(long)(k0 + k) * lda + gm] : 0.f;
            }
        } else {
#pragma unroll
            for (int t = tid; t < BM * BK; t += 256) {
                int m = t / BK, k = t % BK;
                int gm = m0 + m;
                As[k][m] = (gm < M) ? A[(long)gm * lda + (k0 + k)] : 0.f;
            }
        }
        // ---- load B tile ----
        if (TB) {
#pragma unroll
            for (int t = tid; t < BN * BK; t += 256) {
                int n = t / BK, k = t % BK;
                int gn = n0 + n;
                Bs[k][n] = (gn < N) ? Bm[(long)gn * ldb + (k0 + k)] : 0.f;
            }
        } else {
#pragma unroll
            for (int t = tid; t < BK * BN; t += 256) {
                int k = t / BN, n = t % BN;
                int gn = n0 + n;
                Bs[k][n] = (gn < N) ? Bm[(long)(k0 + k) * ldb + gn] : 0.f;
            }
        }
        __syncthreads();

#pragma unroll
        for (int k = 0; k < BK; k++) {
            const float4* a4 = reinterpret_cast<const float4*>(&As[k][ty * TM]);
            float4 a0 = a4[0], a1 = a4[1];
            float4 b0 = *reinterpret_cast<const float4*>(&Bs[k][tx * TN]);
            float ra[TM] = {a0.x, a0.y, a0.z, a0.w, a1.x, a1.y, a1.z, a1.w};
            float rb[TN] = {b0.x, b0.y, b0.z, b0.w};
#pragma unroll
            for (int i = 0; i < TM; i++)
#pragma unroll
                for (int j = 0; j < TN; j++) acc[i][j] += ra[i] * rb[j];
        }
        __syncthreads();
    }

#pragma unroll
    for (int i = 0; i < TM; i++) {
        int gm = m0 + ty * TM + i;
        if (gm >= M) continue;
#pragma unroll
        for (int j = 0; j < TN; j++) {
            int gn = n0 + tx * TN + j;
            if (gn >= N) continue;
            float v = acc[i][j];
            if (BIAS == 1) v += bptr[gn];
            if (BIAS == 2) v += bptr[gm];
            if (RELU) v = fmaxf(v, 0.f);
            Cm[(long)gm * ldc + gn] = v;
        }
    }
}

// ---------------- heat: per-pixel 256-d dot + exp ----------------------------
__global__ void heat_kernel(const float* __restrict__ h,     // (B*P, HW, 256)
                            const float* __restrict__ hm2_w, // (P, 256)
                            const float* __restrict__ hm2_b, // (P,)
                            float* __restrict__ heat)        // (B*P, HW)
{
    int gw = (blockIdx.x * blockDim.x + threadIdx.x) >> 5;
    int lane = threadIdx.x & 31;
    if (gw >= B_ * P_ * HW_) return;
    int z = gw / HW_;          // b*P + p
    int p = z % P_;
    const float* hr = h + (long)gw * 256;
    const float* wv = hm2_w + p * 256;
    float s = 0.f;
#pragma unroll
    for (int j = 0; j < 8; j++) s += hr[lane + j * 32] * wv[lane + j * 32];
#pragma unroll
    for (int o = 16; o; o >>= 1) s += __shfl_xor_sync(0xffffffffu, s, o);
    if (lane == 0) heat[gw] = expf(s + hm2_b[p]);
}

// ---------------- deformable bilinear gather --------------------------------
// One warp per (b, p, output pixel). Lanes split the 256 channels.
__global__ void sample_kernel(const float* __restrict__ ef,    // (B, HW, 512)
                              const float* __restrict__ heat,  // (B*P, HW)
                              const float* __restrict__ offs,  // (B, P*KB*2, HW)
                              float* __restrict__ outs)        // (B, HW, 512)
{
    int gw = (blockIdx.x * blockDim.x + threadIdx.x) >> 5;
    int lane = threadIdx.x & 31;
    if (gw >= B_ * P_ * HW_) return;
    int i  = gw % HW_;
    int bp = gw / HW_;
    int p  = bp % P_;
    int b  = bp / P_;
    int y = i / W_, x = i % W_;

    float num[8];
#pragma unroll
    for (int j = 0; j < 8; j++) num[j] = 0.f;
    float den = 0.f;

    const float* efb   = ef + ((long)b * HW_) * DEXP + p * C_;
    const float* heatb = heat + (long)bp * HW_;
    const float* offb  = offs + ((long)b * (P_ * KB_ * 2) + p * KB_ * 2) * HW_;

#pragma unroll
    for (int k = 0; k < KB_; k++) {
        float ys = (float)y + offb[(k * 2 + 0) * HW_ + i];
        float xs = (float)x + offb[(k * 2 + 1) * HW_ + i];
        float y0f = floorf(ys), x0f = floorf(xs);
#pragma unroll
        for (int c4 = 0; c4 < 4; c4++) {
            float yi = y0f + (float)(c4 >> 1);
            float xi = x0f + (float)(c4 & 1);
            if (yi < 0.f || yi > (float)(H_ - 1) || xi < 0.f || xi > (float)(W_ - 1))
                continue;
            float w = (1.f - fabsf(ys - yi)) * (1.f - fabsf(xs - xi));
            int src = (int)yi * W_ + (int)xi;
            float wh = w * heatb[src];
            den += wh;
            const float* e = efb + (long)src * DEXP;
#pragma unroll
            for (int j = 0; j < 8; j++) num[j] += wh * e[lane + j * 32];
        }
    }
    float inv = 1.f / (den + 1e-6f);
    float* o = outs + ((long)b * HW_ + i) * DEXP + p * C_;
#pragma unroll
    for (int j = 0; j < 8; j++) o[lane + j * 32] = num[j] * inv;
}

// ---------------- GroupNorm stats + normalize -------------------------------
__global__ void gn_stats(const float* __restrict__ merged, float* __restrict__ stat)
{
    int bg = blockIdx.x;           // b*32 + g
    const float* base = merged + (long)bg * 8 * HW_;   // group's 8 channels contiguous
    const int n = 8 * HW_;
    float s = 0.f, s2 = 0.f;
    for (int t = threadIdx.x; t < n; t += 256) {
        float v = base[t];
        s += v; s2 += v * v;
    }
    __shared__ float sh[2][256];
    sh[0][threadIdx.x] = s; sh[1][threadIdx.x] = s2;
    __syncthreads();
    for (int o = 128; o; o >>= 1) {
        if (threadIdx.x < o) {
            sh[0][threadIdx.x] += sh[0][threadIdx.x + o];
            sh[1][threadIdx.x] += sh[1][threadIdx.x + o];
        }
        __syncthreads();
    }
    if (threadIdx.x == 0) {
        float mu  = sh[0][0] / n;
        float var = sh[1][0] / n - mu * mu;
        stat[bg * 2 + 0] = mu;
        stat[bg * 2 + 1] = rsqrtf(var + 1e-5f);
    }
}

__global__ void gn_norm(const float* __restrict__ merged,
                        const float* __restrict__ stat,
                        const float* __restrict__ gn_g,
                        const float* __restrict__ gn_b,
                        float* __restrict__ out)
{
    long idx = (long)blockIdx.x * 256 + threadIdx.x;
    const long total = (long)B_ * C_ * HW_;
    if (idx >= total) return;
    int c = (int)((idx / HW_) % C_);
    int b = (int)(idx / ((long)C_ * HW_));
    int g = c >> 3;
    float mu   = stat[(b * 32 + g) * 2 + 0];
    float rstd = stat[(b * 32 + g) * 2 + 1];
    float v = (merged[idx] - mu) * rstd * gn_g[c] + gn_b[c];
    out[idx] = fmaxf(v, 0.f);
}

// ---------------- launch ------------------------------------------------------
extern "C" void kernel_launch(void* const* d_in, const int* in_sizes, int n_in,
                              void* d_out, int out_size)
{
    const float* x       = (const float*)d_in[0];   // (B, C, H, W)
    const float* offsets = (const float*)d_in[1];   // (B, P*KB*2, H, W)
    const float* ef_w    = (const float*)d_in[2];   // (512, 256)
    const float* ef_b    = (const float*)d_in[3];   // (512,)
    const float* hm1_w   = (const float*)d_in[4];   // (P, 256, 256)
    const float* hm1_b   = (const float*)d_in[5];   // (P, 256)
    const float* hm2_w   = (const float*)d_in[6];   // (P, 256)
    const float* hm2_b   = (const float*)d_in[7];   // (P,)
    const float* merge_w = (const float*)d_in[8];   // (256, 512)
    const float* merge_b = (const float*)d_in[9];   // (256,)
    const float* gn_g    = (const float*)d_in[10];  // (256,)
    const float* gn_b    = (const float*)d_in[11];  // (256,)
    float* out = (float*)d_out;

    float *ef, *buf2, *heat, *merged, *stat;
    cudaGetSymbolAddress((void**)&ef,     g_ef);
    cudaGetSymbolAddress((void**)&buf2,   g_buf2);
    cudaGetSymbolAddress((void**)&heat,   g_heat);
    cudaGetSymbolAddress((void**)&merged, g_merged);
    cudaGetSymbolAddress((void**)&stat,   g_stat);

    // GEMM1: ef_t[b][i][d] = sum_c x[b][c][i] * ef_w[d][c] + ef_b[d]
    // M=HW (i), N=512 (d), K=256 (c). A = x (stored [K][M]), B = ef_w (stored [N][K]).
    {
        dim3 grid((DEXP + BN - 1) / BN, (HW_ + BM - 1) / BM, B_);
        sgemm<true, true, 1, false><<<grid, 256>>>(
            x, HW_, (long)C_ * HW_, 0,
            ef_w, C_, 0, 0,
            ef, DEXP, (long)HW_ * DEXP, 0,
            ef_b, 0, 0,
            1, HW_, DEXP, C_);
    }

    // GEMM2: h[(b,p)][i][d] = relu( sum_c ef_t[b][i][p*256+c] * hm1_w[p][d][c] + hm1_b[p][d] )
    {
        dim3 grid((C_ + BN - 1) / BN, (HW_ + BM - 1) / BM, B_ * P_);
        sgemm<false, true, 1, true><<<grid, 256>>>(
            ef, DEXP, (long)HW_ * DEXP, (long)C_,
            hm1_w, C_, 0, (long)C_ * C_,
            buf2, C_, (long)P_ * HW_ * C_, (long)HW_ * C_,
            hm1_b, 0, (long)C_,
            P_, HW_, C_, C_);
    }

    // heat
    {
        int warps = B_ * P_ * HW_;
        heat_kernel<<<(warps * 32 + 255) / 256, 256>>>(buf2, hm2_w, hm2_b, heat);
    }

    // deformable bilinear gather -> outs (reuses buf2; h fully consumed above)
    {
        int warps = B_ * P_ * HW_;
        sample_kernel<<<(warps * 32 + 255) / 256, 256>>>(ef, heat, offsets, buf2);
    }

    // GEMM3: merged[b][dout][i] = sum_d merge_w[dout][d] * outs[b][i][d] + merge_b[dout]
    // M=256 (dout), N=HW (i), K=512.
    {
        dim3 grid((HW_ + BN - 1) / BN, (C_ + BM - 1) / BM, B_);
        sgemm<false, true, 2, false><<<grid, 256>>>(
            merge_w, DEXP, 0, 0,
            buf2, DEXP, (long)HW_ * DEXP, 0,
            merged, HW_, (long)C_ * HW_, 0,
            merge_b, 0, 0,
            1, C_, HW_, DEXP);
    }

    // GroupNorm + ReLU
    gn_stats<<<B_ * 32, 256>>>(merged, stat);
    {
        long total = (long)B_ * C_ * HW_;
        gn_norm<<<(int)((total + 255) / 256), 256>>>(merged, stat, gn_g, gn_b, out);
    }
}

// round 3
// speedup vs baseline: 1.5246x; 1.5246x over previous
#include <cuda_runtime.h>
#include <cuda_bf16.h>
#include <cstdint>
#include <math.h>

#define B_   2
#define C_   256
#define H_   100
#define W_   152
#define HW_  (H_*W_)
#define P_   2
#define KB_  5          // bins
#define DEXP (P_*C_)    // 512

// ---------------- scratch (static device memory; no allocation) -------------
__device__ float g_ef   [(size_t)B_*HW_*DEXP];   // (B, HW, 512) pixel-major expand feat
__device__ float g_buf2 [(size_t)B_*HW_*DEXP];   // h: (B*P, HW, 256) then outs: (B, HW, 512)
__device__ float g_heat [B_*P_*HW_];             // (B*P, HW)
__device__ float g_merged[(size_t)B_*C_*HW_];    // merged (B, C, HW)
__device__ float g_stat [B_*32*2];               // (b,g) -> mu, rstd

// ======================= bf16x3 mma.sync GEMM ================================
// D[M,N] = A[M,K] * B[N,K]^T (+bias)(+relu), fp32 in/out.
// Each operand split hi/lo bf16; D = Ah*Bh + Ah*Bl + Al*Bh  (error ~2^-16).
#define GBM 128
#define GBN 128
#define GBK 32
#define ROWB   80                  // smem bytes per row (40 bf16; odd 16B stride -> no LDSM conflicts)
#define TILE_B (128*ROWB)          // one bf16 tile: 10240 B
#define BUF_B  (4*TILE_B)          // Ah, Al, Bh, Bl
#define GEMM_SMEM (2*BUF_B)        // double buffered: 81920 B

__device__ __forceinline__ uint32_t smem_u32(const void* p) {
    uint32_t a;
    asm("{ .reg .u64 t; cvta.to.shared.u64 t, %1; cvt.u32.u64 %0, t; }" : "=r"(a) : "l"(p));
    return a;
}
__device__ __forceinline__ void ldsm_x4(uint32_t* r, uint32_t a) {
    asm volatile("ldmatrix.sync.aligned.m8n8.x4.shared.b16 {%0,%1,%2,%3}, [%4];"
        : "=r"(r[0]), "=r"(r[1]), "=r"(r[2]), "=r"(r[3]) : "r"(a));
}
__device__ __forceinline__ void mma_bf16(float* d, const uint32_t* a, const uint32_t* b) {
    asm volatile("mma.sync.aligned.m16n8k16.row.col.f32.bf16.bf16.f32 "
        "{%0,%1,%2,%3}, {%4,%5,%6,%7}, {%8,%9}, {%0,%1,%2,%3};"
        : "+f"(d[0]), "+f"(d[1]), "+f"(d[2]), "+f"(d[3])
        : "r"(a[0]), "r"(a[1]), "r"(a[2]), "r"(a[3]), "r"(b[0]), "r"(b[1]));
}
__device__ __forceinline__ void cvt_split(float f, unsigned short& h, unsigned short& l) {
    __nv_bfloat16 hb = __float2bfloat16(f);
    __nv_bfloat16 lb = __float2bfloat16(f - __bfloat162float(hb));
    h = __bfloat16_as_ushort(hb);
    l = __bfloat16_as_ushort(lb);
}
// convert float4 -> 8B hi + 8B lo, store at (row, c4) of a tile
__device__ __forceinline__ void store_split4(char* sm, int off_h, int off_l,
                                             int row, int c4, float4 v) {
    unsigned short h0,l0,h1,l1,h2,l2,h3,l3;
    cvt_split(v.x, h0, l0); cvt_split(v.y, h1, l1);
    cvt_split(v.z, h2, l2); cvt_split(v.w, h3, l3);
    uint2 hh = make_uint2((uint32_t)h0 | ((uint32_t)h1 << 16),
                          (uint32_t)h2 | ((uint32_t)h3 << 16));
    uint2 ll = make_uint2((uint32_t)l0 | ((uint32_t)l1 << 16),
                          (uint32_t)l2 | ((uint32_t)l3 << 16));
    int off = row * ROWB + c4 * 8;
    *reinterpret_cast<uint2*>(sm + off_h + off) = hh;
    *reinterpret_cast<uint2*>(sm + off_l + off) = ll;
}

// TRANS_A: A stored [K][M] in global (GEMM1 reads x directly).
// BIAS_MODE: 1 = per-col (bptr[gn]), 2 = per-row (bptr[gm]).
template<bool TRANS_A, int BIAS_MODE, bool RELU>
__global__ __launch_bounds__(256, 1)
void tc_gemm(const float* __restrict__ A, int lda, long sA1, long sA2,
             const float* __restrict__ Bm, int ldb, long sB1, long sB2,
             float* __restrict__ Cm, int ldc, long sC1, long sC2,
             const float* __restrict__ bias, long sb1, long sb2,
             int zdiv, int M, int N, int K)
{
    extern __shared__ char smem[];
    const uint32_t sbase = smem_u32(smem);
    const int tid = threadIdx.x;
    const int lane = tid & 31, wid = tid >> 5;

    const int z = blockIdx.z;
    const int z1 = z / zdiv, z2 = z % zdiv;
    A  += z1 * sA1 + z2 * sA2;
    Bm += z1 * sB1 + z2 * sB2;
    Cm += z1 * sC1 + z2 * sC2;
    const float* bptr = bias + z1 * sb1 + z2 * sb2;

    const int m0 = blockIdx.y * GBM;
    const int n0 = blockIdx.x * GBN;

    const int wm = wid & 3;          // 4 warps over M
    const int wn = wid >> 2;         // 2 warps over N
    const int lane8 = lane & 7, sel = lane >> 3;

    float acc[2][8][4];
#pragma unroll
    for (int i = 0; i < 2; i++)
#pragma unroll
        for (int j = 0; j < 8; j++)
#pragma unroll
            for (int q = 0; q < 4; q++) acc[i][j][q] = 0.f;

    const int nk = K / GBK;
    float4 st[8];

    // ---- tile loader: global -> regs ----
    auto LOAD = [&](int kt) {
        const int k0 = kt * GBK;
#pragma unroll
        for (int j = 0; j < 4; j++) {
            int lin = tid + j * 256;
            if (TRANS_A) {
                int kk = lin >> 5, mm = (lin & 31) * 4;
                int gm = m0 + mm;
                st[j] = (gm < M) ? *reinterpret_cast<const float4*>(A + (long)(k0 + kk) * lda + gm)
                                 : make_float4(0.f, 0.f, 0.f, 0.f);
            } else {
                int row = lin >> 3, c4 = lin & 7;
                int gm = m0 + row;
                st[j] = (gm < M) ? *reinterpret_cast<const float4*>(A + (long)gm * lda + k0 + c4 * 4)
                                 : make_float4(0.f, 0.f, 0.f, 0.f);
            }
        }
#pragma unroll
        for (int j = 0; j < 4; j++) {
            int lin = tid + j * 256;
            int row = lin >> 3, c4 = lin & 7;
            int gn = n0 + row;
            st[4 + j] = (gn < N) ? *reinterpret_cast<const float4*>(Bm + (long)gn * ldb + k0 + c4 * 4)
                                 : make_float4(0.f, 0.f, 0.f, 0.f);
        }
    };
    // ---- regs -> smem (split hi/lo) ----
    auto STORE = [&](int bsel) {
        char* base = smem + bsel * BUF_B;
#pragma unroll
        for (int j = 0; j < 4; j++) {
            int lin = tid + j * 256;
            if (TRANS_A) {
                int kk = lin >> 5, mm = (lin & 31) * 4;
                float v[4] = {st[j].x, st[j].y, st[j].z, st[j].w};
#pragma unroll
                for (int i = 0; i < 4; i++) {
                    unsigned short h, l;
                    cvt_split(v[i], h, l);
                    int off = (mm + i) * ROWB + kk * 2;
                    *reinterpret_cast<unsigned short*>(base + off) = h;
                    *reinterpret_cast<unsigned short*>(base + TILE_B + off) = l;
                }
            } else {
                int row = lin >> 3, c4 = lin & 7;
                store_split4(base, 0, TILE_B, row, c4, st[j]);
            }
        }
#pragma unroll
        for (int j = 0; j < 4; j++) {
            int lin = tid + j * 256;
            int row = lin >> 3, c4 = lin & 7;
            store_split4(base, 2 * TILE_B, 3 * TILE_B, row, c4, st[4 + j]);
        }
    };
    // ---- compute one tile from smem buffer bsel ----
    auto COMPUTE = [&](int bsel) {
        const uint32_t ah_b = sbase + bsel * BUF_B;
        const uint32_t al_b = ah_b + TILE_B;
        const uint32_t bh_b = ah_b + 2 * TILE_B;
        const uint32_t bl_b = ah_b + 3 * TILE_B;
#pragma unroll
        for (int ks = 0; ks < 2; ks++) {
            const int kb = ks * 16;
            uint32_t ah[2][4], al[2][4];
#pragma unroll
            for (int mf = 0; mf < 2; mf++) {
                int row = wm * 32 + mf * 16 + lane8 + (sel & 1) * 8;
                int kc  = kb + (sel & 2) * 4;
                uint32_t off = (uint32_t)(row * ROWB + kc * 2);
                ldsm_x4(ah[mf], ah_b + off);
                ldsm_x4(al[mf], al_b + off);
            }
#pragma unroll
            for (int nf2 = 0; nf2 < 4; nf2++) {
                int nrow = wn * 64 + nf2 * 16 + lane8 + (sel & 2) * 4;
                int kc   = kb + (sel & 1) * 8;
                uint32_t off = (uint32_t)(nrow * ROWB + kc * 2);
                uint32_t bh4[4], bl4[4];
                ldsm_x4(bh4, bh_b + off);
                ldsm_x4(bl4, bl_b + off);
#pragma unroll
                for (int half = 0; half < 2; half++) {
                    const uint32_t* bh = bh4 + half * 2;
                    const uint32_t* bl = bl4 + half * 2;
#pragma unroll
                    for (int mf = 0; mf < 2; mf++) {
                        float* d = acc[mf][nf2 * 2 + half];
                        mma_bf16(d, ah[mf], bh);
                        mma_bf16(d, ah[mf], bl);
                        mma_bf16(d, al[mf], bh);
                    }
                }
            }
        }
    };

    LOAD(0); STORE(0);
    __syncthreads();
    for (int kt = 0; kt < nk; kt++) {
        if (kt + 1 < nk) LOAD(kt + 1);
        COMPUTE(kt & 1);
        if (kt + 1 < nk) STORE((kt + 1) & 1);
        __syncthreads();
    }

    // ---- epilogue ----
    const int g = lane >> 2, t = lane & 3;
#pragma unroll
    for (int mf = 0; mf < 2; mf++) {
#pragma unroll
        for (int nf = 0; nf < 8; nf++) {
            const float* d = acc[mf][nf];
            int gm0 = m0 + wm * 32 + mf * 16 + g;
            int gn  = n0 + wn * 64 + nf * 8 + 2 * t;
            if (gn >= N) continue;
            float bc0 = 0.f, bc1 = 0.f;
            if (BIAS_MODE == 1) { bc0 = bptr[gn]; bc1 = bptr[gn + 1]; }
#pragma unroll
            for (int rr = 0; rr < 2; rr++) {
                int gm = gm0 + rr * 8;
                if (gm >= M) continue;
                float v0 = d[rr * 2 + 0], v1 = d[rr * 2 + 1];
                if (BIAS_MODE == 1) { v0 += bc0; v1 += bc1; }
                else { float br = bptr[gm]; v0 += br; v1 += br; }
                if (RELU) { v0 = fmaxf(v0, 0.f); v1 = fmaxf(v1, 0.f); }
                *reinterpret_cast<float2*>(Cm + (long)gm * ldc + gn) = make_float2(v0, v1);
            }
        }
    }
}

// ---------------- heat: per-pixel 256-d dot + exp ----------------------------
__global__ void heat_kernel(const float* __restrict__ h,     // (B*P, HW, 256)
                            const float* __restrict__ hm2_w, // (P, 256)
                            const float* __restrict__ hm2_b, // (P,)
                            float* __restrict__ heat)        // (B*P, HW)
{
    int gw = (blockIdx.x * blockDim.x + threadIdx.x) >> 5;
    int lane = threadIdx.x & 31;
    if (gw >= B_ * P_ * HW_) return;
    int zz = gw / HW_;
    int p = zz % P_;
    const float* hr = h + (long)gw * 256;
    const float* wv = hm2_w + p * 256;
    float s = 0.f;
#pragma unroll
    for (int j = 0; j < 8; j++) s += hr[lane + j * 32] * wv[lane + j * 32];
#pragma unroll
    for (int o = 16; o; o >>= 1) s += __shfl_xor_sync(0xffffffffu, s, o);
    if (lane == 0) heat[gw] = expf(s + hm2_b[p]);
}

// ---------------- deformable bilinear gather --------------------------------
__global__ void sample_kernel(const float* __restrict__ ef,    // (B, HW, 512)
                              const float* __restrict__ heat,  // (B*P, HW)
                              const float* __restrict__ offs,  // (B, P*KB*2, HW)
                              float* __restrict__ outs)        // (B, HW, 512)
{
    int gw = (blockIdx.x * blockDim.x + threadIdx.x) >> 5;
    int lane = threadIdx.x & 31;
    if (gw >= B_ * P_ * HW_) return;
    int i  = gw % HW_;
    int bp = gw / HW_;
    int p  = bp % P_;
    int b  = bp / P_;
    int y = i / W_, x = i % W_;

    float num[8];
#pragma unroll
    for (int j = 0; j < 8; j++) num[j] = 0.f;
    float den = 0.f;

    const float* efb   = ef + ((long)b * HW_) * DEXP + p * C_;
    const float* heatb = heat + (long)bp * HW_;
    const float* offb  = offs + ((long)b * (P_ * KB_ * 2) + p * KB_ * 2) * HW_;

#pragma unroll
    for (int k = 0; k < KB_; k++) {
        float ys = (float)y + offb[(k * 2 + 0) * HW_ + i];
        float xs = (float)x + offb[(k * 2 + 1) * HW_ + i];
        float y0f = floorf(ys), x0f = floorf(xs);
#pragma unroll
        for (int c4 = 0; c4 < 4; c4++) {
            float yi = y0f + (float)(c4 >> 1);
            float xi = x0f + (float)(c4 & 1);
            if (yi < 0.f || yi > (float)(H_ - 1) || xi < 0.f || xi > (float)(W_ - 1))
                continue;
            float w = (1.f - fabsf(ys - yi)) * (1.f - fabsf(xs - xi));
            int src = (int)yi * W_ + (int)xi;
            float wh = w * heatb[src];
            den += wh;
            const float* e = efb + (long)src * DEXP;
#pragma unroll
            for (int j = 0; j < 8; j++) num[j] += wh * e[lane + j * 32];
        }
    }
    float inv = 1.f / (den + 1e-6f);
    float* o = outs + ((long)b * HW_ + i) * DEXP + p * C_;
#pragma unroll
    for (int j = 0; j < 8; j++) o[lane + j * 32] = num[j] * inv;
}

// ---------------- GroupNorm stats + normalize -------------------------------
__global__ void gn_stats(const float* __restrict__ merged, float* __restrict__ stat)
{
    int bg = blockIdx.x;
    const float* base = merged + (long)bg * 8 * HW_;
    const int n = 8 * HW_;
    float s = 0.f, s2 = 0.f;
    for (int t = threadIdx.x; t < n; t += 256) {
        float v = base[t];
        s += v; s2 += v * v;
    }
    __shared__ float sh[2][256];
    sh[0][threadIdx.x] = s; sh[1][threadIdx.x] = s2;
    __syncthreads();
    for (int o = 128; o; o >>= 1) {
        if (threadIdx.x < o) {
            sh[0][threadIdx.x] += sh[0][threadIdx.x + o];
            sh[1][threadIdx.x] += sh[1][threadIdx.x + o];
        }
        __syncthreads();
    }
    if (threadIdx.x == 0) {
        float mu  = sh[0][0] / n;
        float var = sh[1][0] / n - mu * mu;
        stat[bg * 2 + 0] = mu;
        stat[bg * 2 + 1] = rsqrtf(var + 1e-5f);
    }
}

__global__ void gn_norm(const float* __restrict__ merged,
                        const float* __restrict__ stat,
                        const float* __restrict__ gn_g,
                        const float* __restrict__ gn_b,
                        float* __restrict__ out)
{
    long idx = (long)blockIdx.x * 256 + threadIdx.x;
    const long total = (long)B_ * C_ * HW_;
    if (idx >= total) return;
    int c = (int)((idx / HW_) % C_);
    int b = (int)(idx / ((long)C_ * HW_));
    int g = c >> 3;
    float mu   = stat[(b * 32 + g) * 2 + 0];
    float rstd = stat[(b * 32 + g) * 2 + 1];
    float v = (merged[idx] - mu) * rstd * gn_g[c] + gn_b[c];
    out[idx] = fmaxf(v, 0.f);
}

// ---------------- launch ------------------------------------------------------
extern "C" void kernel_launch(void* const* d_in, const int* in_sizes, int n_in,
                              void* d_out, int out_size)
{
    const float* x       = (const float*)d_in[0];   // (B, C, H, W)
    const float* offsets = (const float*)d_in[1];   // (B, P*KB*2, H, W)
    const float* ef_w    = (const float*)d_in[2];   // (512, 256)
    const float* ef_b    = (const float*)d_in[3];   // (512,)
    const float* hm1_w   = (const float*)d_in[4];   // (P, 256, 256)
    const float* hm1_b   = (const float*)d_in[5];   // (P, 256)
    const float* hm2_w   = (const float*)d_in[6];   // (P, 256)
    const float* hm2_b   = (const float*)d_in[7];   // (P,)
    const float* merge_w = (const float*)d_in[8];   // (256, 512)
    const float* merge_b = (const float*)d_in[9];   // (256,)
    const float* gn_g    = (const float*)d_in[10];  // (256,)
    const float* gn_b    = (const float*)d_in[11];  // (256,)
    float* out = (float*)d_out;

    float *ef, *buf2, *heat, *merged, *stat;
    cudaGetSymbolAddress((void**)&ef,     g_ef);
    cudaGetSymbolAddress((void**)&buf2,   g_buf2);
    cudaGetSymbolAddress((void**)&heat,   g_heat);
    cudaGetSymbolAddress((void**)&merged, g_merged);
    cudaGetSymbolAddress((void**)&stat,   g_stat);

    cudaFuncSetAttribute(tc_gemm<true,  1, false>, cudaFuncAttributeMaxDynamicSharedMemorySize, GEMM_SMEM);
    cudaFuncSetAttribute(tc_gemm<false, 1, true >, cudaFuncAttributeMaxDynamicSharedMemorySize, GEMM_SMEM);
    cudaFuncSetAttribute(tc_gemm<false, 2, false>, cudaFuncAttributeMaxDynamicSharedMemorySize, GEMM_SMEM);

    // 1) GEMM1: ef[b][i][d] = sum_c x[b][c][i] * ef_w[d][c] + ef_b[d]
    //    M=HW (i), N=512 (d), K=256 (c); A = x stored [K][M] (TRANS_A).
    {
        dim3 grid((DEXP + GBN - 1) / GBN, (HW_ + GBM - 1) / GBM, B_);
        tc_gemm<true, 1, false><<<grid, 256, GEMM_SMEM>>>(
            x, HW_, (long)C_ * HW_, 0,
            ef_w, C_, 0, 0,
            ef, DEXP, (long)HW_ * DEXP, 0,
            ef_b, 0, 0,
            1, HW_, DEXP, C_);
    }

    // 2) GEMM2: h[(b,p)][i][d] = relu(sum_c ef[b][i][p*256+c]*hm1_w[p][d][c] + hm1_b[p][d])
    {
        dim3 grid((C_ + GBN - 1) / GBN, (HW_ + GBM - 1) / GBM, B_ * P_);
        tc_gemm<false, 1, true><<<grid, 256, GEMM_SMEM>>>(
            ef, DEXP, (long)HW_ * DEXP, (long)C_,
            hm1_w, C_, 0, (long)C_ * C_,
            buf2, C_, (long)P_ * HW_ * C_, (long)HW_ * C_,
            hm1_b, 0, (long)C_,
            P_, HW_, C_, C_);
    }

    // 3) heat
    {
        int warps = B_ * P_ * HW_;
        heat_kernel<<<(warps * 32 + 255) / 256, 256>>>(buf2, hm2_w, hm2_b, heat);
    }

    // 4) deformable bilinear gather -> outs (reuses buf2)
    {
        int warps = B_ * P_ * HW_;
        sample_kernel<<<(warps * 32 + 255) / 256, 256>>>(ef, heat, offsets, buf2);
    }

    // 5) GEMM3: merged[b][dout][i] = sum_d merge_w[dout][d]*outs[b][i][d] + merge_b[dout]
    //    M=256 (dout), N=HW (i), K=512.
    {
        dim3 grid((HW_ + GBN - 1) / GBN, (C_ + GBM - 1) / GBM, B_);
        tc_gemm<false, 2, false><<<grid, 256, GEMM_SMEM>>>(
            merge_w, DEXP, 0, 0,
            buf2, DEXP, (long)HW_ * DEXP, 0,
            merged, HW_, (long)C_ * HW_, 0,
            merge_b, 0, 0,
            1, C_, HW_, DEXP);
    }

    // 6) GroupNorm + ReLU
    gn_stats<<<B_ * 32, 256>>>(merged, stat);
    {
        long total = (long)B_ * C_ * HW_;
        gn_norm<<<(int)((total + 255) / 256), 256>>>(merged, stat, gn_g, gn_b, out);
    }
}

// round 4
// speedup vs baseline: 1.8726x; 1.2283x over previous
#include <cuda_runtime.h>
#include <cuda_bf16.h>
#include <cstdint>
#include <math.h>

#define B_   2
#define C_   256
#define H_   100
#define W_   152
#define HW_  (H_*W_)
#define P_   2
#define KB_  5          // bins
#define DEXP (P_*C_)    // 512

// ---------------- scratch (static device memory; no allocation) -------------
__device__ float         g_ef   [(size_t)B_*HW_*DEXP];   // (B, HW, 512) fp32 for gather
__device__ __nv_bfloat16 g_efs_h[(size_t)B_*HW_*DEXP];   // ef split hi
__device__ __nv_bfloat16 g_efs_l[(size_t)B_*HW_*DEXP];   // ef split lo
__device__ __nv_bfloat16 g_out_h[(size_t)B_*HW_*DEXP];   // gather out split hi
__device__ __nv_bfloat16 g_out_l[(size_t)B_*HW_*DEXP];   // gather out split lo
__device__ __nv_bfloat16 g_xs_h [(size_t)B_*HW_*C_];     // x transposed+split hi
__device__ __nv_bfloat16 g_xs_l [(size_t)B_*HW_*C_];
#define WOFF_EF   0
#define WOFF_HM1  (DEXP*C_)                  // 131072
#define WOFF_MRG  (DEXP*C_ + P_*C_*C_)       // 262144
__device__ __nv_bfloat16 g_w_h  [DEXP*C_ + P_*C_*C_ + C_*DEXP];
__device__ __nv_bfloat16 g_w_l  [DEXP*C_ + P_*C_*C_ + C_*DEXP];
__device__ float g_heat [B_*P_*HW_];
__device__ float g_hacc [B_*P_*HW_];
__device__ float g_merged[(size_t)B_*C_*HW_];
__device__ float g_stat [B_*32*2];

// ======================= helpers =============================================
__device__ __forceinline__ uint32_t smem_u32(const void* p) {
    uint32_t a;
    asm("{ .reg .u64 t; cvta.to.shared.u64 t, %1; cvt.u32.u64 %0, t; }" : "=r"(a) : "l"(p));
    return a;
}
__device__ __forceinline__ void ldsm_x4(uint32_t* r, uint32_t a) {
    asm volatile("ldmatrix.sync.aligned.m8n8.x4.shared.b16 {%0,%1,%2,%3}, [%4];"
        : "=r"(r[0]), "=r"(r[1]), "=r"(r[2]), "=r"(r[3]) : "r"(a));
}
__device__ __forceinline__ void mma_bf16(float* d, const uint32_t* a, const uint32_t* b) {
    asm volatile("mma.sync.aligned.m16n8k16.row.col.f32.bf16.bf16.f32 "
        "{%0,%1,%2,%3}, {%4,%5,%6,%7}, {%8,%9}, {%0,%1,%2,%3};"
        : "+f"(d[0]), "+f"(d[1]), "+f"(d[2]), "+f"(d[3])
        : "r"(a[0]), "r"(a[1]), "r"(a[2]), "r"(a[3]), "r"(b[0]), "r"(b[1]));
}
__device__ __forceinline__ void cvt_split(float f, unsigned short& h, unsigned short& l) {
    __nv_bfloat16 hb = __float2bfloat16(f);
    __nv_bfloat16 lb = __float2bfloat16(f - __bfloat162float(hb));
    h = __bfloat16_as_ushort(hb);
    l = __bfloat16_as_ushort(lb);
}
__device__ __forceinline__ void cp_async16(uint32_t dst, const void* src, int src_bytes) {
    asm volatile("cp.async.cg.shared.global [%0], [%1], 16, %2;"
        :: "r"(dst), "l"(src), "r"(src_bytes) : "memory");
}
#define CP_COMMIT() asm volatile("cp.async.commit_group;" ::: "memory")
#define CP_WAIT(n)  asm volatile("cp.async.wait_group %0;" :: "n"(n) : "memory")

// ======================= bf16x3 mma.sync GEMM (pre-split operands) ===========
// D[M,N] = A[M,K] * B[N,K]^T; A,B given as bf16 hi/lo planes, K-major.
// EPI: 0 = fp32 C (+bias +relu); 1 = fp32 C + bf16 hi/lo C planes (GEMM1);
//      2 = no C store; heat fusion: atomicAdd( sum_n relu(c+bias)*w2[n] ).
#define GBM 128
#define GBN 128
#define GBK 32
#define ROWB   80                  // smem row pitch (odd 16B stride -> LDSM conflict-free)
#define TILE_B (128*ROWB)          // 10240 B per plane tile
#define BUF_B  (4*TILE_B)          // Ah, Al, Bh, Bl
#define GEMM_SMEM (2*BUF_B)        // 81920 B double buffered

template<int BIAS_MODE, bool RELU, int EPI>
__global__ __launch_bounds__(256, 1)
void tc_gemm(const __nv_bfloat16* __restrict__ Ah, const __nv_bfloat16* __restrict__ Al,
             int lda, long sA1, long sA2,
             const __nv_bfloat16* __restrict__ Bh, const __nv_bfloat16* __restrict__ Bl,
             int ldb, long sB1, long sB2,
             float* __restrict__ Cm, int ldc, long sC1, long sC2,
             const float* __restrict__ bias, long sb1, long sb2,
             __nv_bfloat16* __restrict__ Ch, __nv_bfloat16* __restrict__ Cl,
             const float* __restrict__ w2, float* __restrict__ hacc,
             int zdiv, int M, int N, int K)
{
    extern __shared__ char smem[];
    const uint32_t sbase = smem_u32(smem);
    const int tid = threadIdx.x;
    const int lane = tid & 31, wid = tid >> 5;

    const int z = blockIdx.z;
    const int z1 = z / zdiv, z2 = z % zdiv;
    Ah += z1 * sA1 + z2 * sA2;  Al += z1 * sA1 + z2 * sA2;
    Bh += z1 * sB1 + z2 * sB2;  Bl += z1 * sB1 + z2 * sB2;
    const float* bptr = bias + z1 * sb1 + z2 * sb2;

    const int m0 = blockIdx.y * GBM;
    const int n0 = blockIdx.x * GBN;

    const int wm = wid & 3;          // 4 warps over M
    const int wn = wid >> 2;         // 2 warps over N
    const int lane8 = lane & 7, sel = lane >> 3;

    float acc[2][8][4];
#pragma unroll
    for (int i = 0; i < 2; i++)
#pragma unroll
        for (int j = 0; j < 8; j++)
#pragma unroll
            for (int q = 0; q < 4; q++) acc[i][j][q] = 0.f;

    const int nk = K / GBK;

    auto LOADCP = [&](int kt) {
        const int k0 = kt * GBK;
        const uint32_t sb = sbase + (kt & 1) * BUF_B;
#pragma unroll
        for (int j = 0; j < 2; j++) {
            int lin = tid + j * 256;           // 0..511
            int row = lin >> 2, q = lin & 3;
            uint32_t off = (uint32_t)(row * ROWB + q * 16);
            int gm = m0 + row, gn = n0 + row;
            int szA = (gm < M) ? 16 : 0;
            int szB = (gn < N) ? 16 : 0;
            long ga = (long)(gm < M ? gm : M - 1) * lda + k0 + q * 8;
            long gb = (long)(gn < N ? gn : N - 1) * ldb + k0 + q * 8;
            cp_async16(sb + off,              Ah + ga, szA);
            cp_async16(sb + TILE_B + off,     Al + ga, szA);
            cp_async16(sb + 2 * TILE_B + off, Bh + gb, szB);
            cp_async16(sb + 3 * TILE_B + off, Bl + gb, szB);
        }
    };

    auto COMPUTE = [&](int bsel) {
        const uint32_t ah_b = sbase + bsel * BUF_B;
        const uint32_t al_b = ah_b + TILE_B;
        const uint32_t bh_b = ah_b + 2 * TILE_B;
        const uint32_t bl_b = ah_b + 3 * TILE_B;
#pragma unroll
        for (int ks = 0; ks < 2; ks++) {
            const int kb = ks * 16;
            uint32_t ah[2][4], al[2][4];
#pragma unroll
            for (int mf = 0; mf < 2; mf++) {
                int row = wm * 32 + mf * 16 + lane8 + (sel & 1) * 8;
                int kc  = kb + (sel & 2) * 4;
                uint32_t off = (uint32_t)(row * ROWB + kc * 2);
                ldsm_x4(ah[mf], ah_b + off);
                ldsm_x4(al[mf], al_b + off);
            }
#pragma unroll
            for (int nf2 = 0; nf2 < 4; nf2++) {
                int nrow = wn * 64 + nf2 * 16 + lane8 + (sel & 2) * 4;
                int kc   = kb + (sel & 1) * 8;
                uint32_t off = (uint32_t)(nrow * ROWB + kc * 2);
                uint32_t bh4[4], bl4[4];
                ldsm_x4(bh4, bh_b + off);
                ldsm_x4(bl4, bl_b + off);
                // pass-major: same-accumulator MMAs are 4 apart (hide latency)
#pragma unroll
                for (int half = 0; half < 2; half++)
#pragma unroll
                    for (int mf = 0; mf < 2; mf++)
                        mma_bf16(acc[mf][nf2 * 2 + half], ah[mf], bh4 + half * 2);
#pragma unroll
                for (int half = 0; half < 2; half++)
#pragma unroll
                    for (int mf = 0; mf < 2; mf++)
                        mma_bf16(acc[mf][nf2 * 2 + half], ah[mf], bl4 + half * 2);
#pragma unroll
                for (int half = 0; half < 2; half++)
#pragma unroll
                    for (int mf = 0; mf < 2; mf++)
                        mma_bf16(acc[mf][nf2 * 2 + half], al[mf], bh4 + half * 2);
            }
        }
    };

    LOADCP(0); CP_COMMIT();
    for (int kt = 0; kt < nk; kt++) {
        if (kt + 1 < nk) { LOADCP(kt + 1); CP_COMMIT(); CP_WAIT(1); }
        else             { CP_WAIT(0); }
        __syncthreads();
        COMPUTE(kt & 1);
        __syncthreads();
    }

    // ---- epilogue ----
    const int g = lane >> 2, t = lane & 3;

    if (EPI == 2) {
        // heat fusion: s[row] = sum_n relu(c + bias[n]) * w2[n], atomicAdd per row
        const float* w2p = w2 + z2 * C_;
        float s[2][2] = {{0.f, 0.f}, {0.f, 0.f}};
#pragma unroll
        for (int nf = 0; nf < 8; nf++) {
            int gn = n0 + wn * 64 + nf * 8 + 2 * t;
            float b0 = bptr[gn], b1 = bptr[gn + 1];
            float w0 = w2p[gn],  w1 = w2p[gn + 1];
#pragma unroll
            for (int mf = 0; mf < 2; mf++)
#pragma unroll
                for (int rr = 0; rr < 2; rr++) {
                    float v0 = fmaxf(acc[mf][nf][rr * 2 + 0] + b0, 0.f);
                    float v1 = fmaxf(acc[mf][nf][rr * 2 + 1] + b1, 0.f);
                    s[mf][rr] += v0 * w0 + v1 * w1;
                }
        }
#pragma unroll
        for (int mf = 0; mf < 2; mf++)
#pragma unroll
            for (int rr = 0; rr < 2; rr++) {
                s[mf][rr] += __shfl_xor_sync(0xffffffffu, s[mf][rr], 1);
                s[mf][rr] += __shfl_xor_sync(0xffffffffu, s[mf][rr], 2);
            }
        if (t == 0) {
            float* hz = hacc + (long)z * HW_;
#pragma unroll
            for (int mf = 0; mf < 2; mf++)
#pragma unroll
                for (int rr = 0; rr < 2; rr++) {
                    int gm = m0 + wm * 32 + mf * 16 + rr * 8 + g;
                    if (gm < M) atomicAdd(hz + gm, s[mf][rr]);
                }
        }
        return;
    }

    Cm += z1 * sC1 + z2 * sC2;
    if (EPI == 1) { Ch += z1 * sC1 + z2 * sC2; Cl += z1 * sC1 + z2 * sC2; }
#pragma unroll
    for (int mf = 0; mf < 2; mf++) {
#pragma unroll
        for (int nf = 0; nf < 8; nf++) {
            const float* d = acc[mf][nf];
            int gm0 = m0 + wm * 32 + mf * 16 + g;
            int gn  = n0 + wn * 64 + nf * 8 + 2 * t;
            if (gn >= N) continue;
            float bc0 = 0.f, bc1 = 0.f;
            if (BIAS_MODE == 1) { bc0 = bptr[gn]; bc1 = bptr[gn + 1]; }
#pragma unroll
            for (int rr = 0; rr < 2; rr++) {
                int gm = gm0 + rr * 8;
                if (gm >= M) continue;
                float v0 = d[rr * 2 + 0], v1 = d[rr * 2 + 1];
                if (BIAS_MODE == 1) { v0 += bc0; v1 += bc1; }
                else { float br = bptr[gm]; v0 += br; v1 += br; }
                if (RELU) { v0 = fmaxf(v0, 0.f); v1 = fmaxf(v1, 0.f); }
                long idx = (long)gm * ldc + gn;
                *reinterpret_cast<float2*>(Cm + idx) = make_float2(v0, v1);
                if (EPI == 1) {
                    unsigned short h0, l0, h1, l1;
                    cvt_split(v0, h0, l0); cvt_split(v1, h1, l1);
                    *reinterpret_cast<uint32_t*>(Ch + idx) =
                        (uint32_t)h0 | ((uint32_t)h1 << 16);
                    *reinterpret_cast<uint32_t*>(Cl + idx) =
                        (uint32_t)l0 | ((uint32_t)l1 << 16);
                }
            }
        }
    }
}

// ---------------- splitters --------------------------------------------------
__global__ void split_w_kernel(const float* __restrict__ w,
                               __nv_bfloat16* __restrict__ h,
                               __nv_bfloat16* __restrict__ l, int n)
{
    int i = blockIdx.x * 256 + threadIdx.x;
    if (i >= n) return;
    unsigned short hh, ll;
    cvt_split(w[i], hh, ll);
    h[i] = __ushort_as_bfloat16(hh);
    l[i] = __ushort_as_bfloat16(ll);
}

// transpose x (B,C,HW) -> split planes (B,HW,C)
__global__ void split_x_kernel(const float* __restrict__ x,
                               __nv_bfloat16* __restrict__ xh,
                               __nv_bfloat16* __restrict__ xl)
{
    __shared__ float tile[32][33];
    int b = blockIdx.z;
    int hw0 = blockIdx.x * 32, c0 = blockIdx.y * 32;
    const float* xb = x + (long)b * C_ * HW_;
    int tx = threadIdx.x, ty = threadIdx.y;   // 32 x 8
#pragma unroll
    for (int i = 0; i < 32; i += 8) {
        int c = c0 + ty + i, hw = hw0 + tx;
        tile[ty + i][tx] = (hw < HW_) ? xb[(long)c * HW_ + hw] : 0.f;
    }
    __syncthreads();
#pragma unroll
    for (int i = 0; i < 32; i += 8) {
        int hw = hw0 + ty + i, c = c0 + tx;
        if (hw < HW_) {
            unsigned short h, l;
            cvt_split(tile[tx][ty + i], h, l);
            long idx = (long)b * HW_ * C_ + (long)hw * C_ + c;
            xh[idx] = __ushort_as_bfloat16(h);
            xl[idx] = __ushort_as_bfloat16(l);
        }
    }
}

__global__ void zero_kernel(float* __restrict__ p, int n)
{
    int i = blockIdx.x * 256 + threadIdx.x;
    if (i < n) p[i] = 0.f;
}

__global__ void heat_exp_kernel(const float* __restrict__ hacc,
                                const float* __restrict__ hm2_b,
                                float* __restrict__ heat)
{
    int i = blockIdx.x * 256 + threadIdx.x;
    if (i >= B_ * P_ * HW_) return;
    int p = (i / HW_) % P_;
    heat[i] = expf(hacc[i] + hm2_b[p]);
}

// ---------------- deformable bilinear gather --------------------------------
__global__ void sample_kernel(const float* __restrict__ ef,    // (B, HW, 512) fp32
                              const float* __restrict__ heat,  // (B*P, HW)
                              const float* __restrict__ offs,  // (B, P*KB*2, HW)
                              __nv_bfloat16* __restrict__ oh,  // split hi (B,HW,512)
                              __nv_bfloat16* __restrict__ ol)  // split lo
{
    int gw = (blockIdx.x * blockDim.x + threadIdx.x) >> 5;
    int lane = threadIdx.x & 31;
    if (gw >= B_ * P_ * HW_) return;
    int i  = gw % HW_;
    int bp = gw / HW_;
    int p  = bp % P_;
    int b  = bp / P_;
    int y = i / W_, x = i % W_;

    float num[8];
#pragma unroll
    for (int j = 0; j < 8; j++) num[j] = 0.f;
    float den = 0.f;

    const float* efb   = ef + ((long)b * HW_) * DEXP + p * C_;
    const float* heatb = heat + (long)bp * HW_;
    const float* offb  = offs + ((long)b * (P_ * KB_ * 2) + p * KB_ * 2) * HW_;

#pragma unroll
    for (int k = 0; k < KB_; k++) {
        float ys = (float)y + offb[(k * 2 + 0) * HW_ + i];
        float xs = (float)x + offb[(k * 2 + 1) * HW_ + i];
        float y0f = floorf(ys), x0f = floorf(xs);
#pragma unroll
        for (int c4 = 0; c4 < 4; c4++) {
            float yi = y0f + (float)(c4 >> 1);
            float xi = x0f + (float)(c4 & 1);
            if (yi < 0.f || yi > (float)(H_ - 1) || xi < 0.f || xi > (float)(W_ - 1))
                continue;
            float w = (1.f - fabsf(ys - yi)) * (1.f - fabsf(xs - xi));
            int src = (int)yi * W_ + (int)xi;
            float wh = w * heatb[src];
            den += wh;
            const float* e = efb + (long)src * DEXP;
#pragma unroll
            for (int j = 0; j < 8; j++) num[j] += wh * e[lane + j * 32];
        }
    }
    float inv = 1.f / (den + 1e-6f);
    long obase = ((long)b * HW_ + i) * DEXP + p * C_ + lane;
#pragma unroll
    for (int j = 0; j < 8; j++) {
        unsigned short h, l;
        cvt_split(num[j] * inv, h, l);
        oh[obase + j * 32] = __ushort_as_bfloat16(h);
        ol[obase + j * 32] = __ushort_as_bfloat16(l);
    }
}

// ---------------- GroupNorm stats + normalize -------------------------------
__global__ void gn_stats(const float* __restrict__ merged, float* __restrict__ stat)
{
    int bg = blockIdx.x;
    const float* base = merged + (long)bg * 8 * HW_;
    const int n = 8 * HW_;
    float s = 0.f, s2 = 0.f;
    for (int t = threadIdx.x; t < n; t += 256) {
        float v = base[t];
        s += v; s2 += v * v;
    }
    __shared__ float sh[2][256];
    sh[0][threadIdx.x] = s; sh[1][threadIdx.x] = s2;
    __syncthreads();
    for (int o = 128; o; o >>= 1) {
        if (threadIdx.x < o) {
            sh[0][threadIdx.x] += sh[0][threadIdx.x + o];
            sh[1][threadIdx.x] += sh[1][threadIdx.x + o];
        }
        __syncthreads();
    }
    if (threadIdx.x == 0) {
        float mu  = sh[0][0] / n;
        float var = sh[1][0] / n - mu * mu;
        stat[bg * 2 + 0] = mu;
        stat[bg * 2 + 1] = rsqrtf(var + 1e-5f);
    }
}

__global__ void gn_norm(const float* __restrict__ merged,
                        const float* __restrict__ stat,
                        const float* __restrict__ gn_g,
                        const float* __restrict__ gn_b,
                        float* __restrict__ out)
{
    long idx = (long)blockIdx.x * 256 + threadIdx.x;
    const long total = (long)B_ * C_ * HW_;
    if (idx >= total) return;
    int c = (int)((idx / HW_) % C_);
    int b = (int)(idx / ((long)C_ * HW_));
    int g = c >> 3;
    float mu   = stat[(b * 32 + g) * 2 + 0];
    float rstd = stat[(b * 32 + g) * 2 + 1];
    float v = (merged[idx] - mu) * rstd * gn_g[c] + gn_b[c];
    out[idx] = fmaxf(v, 0.f);
}

// ---------------- launch ------------------------------------------------------
extern "C" void kernel_launch(void* const* d_in, const int* in_sizes, int n_in,
                              void* d_out, int out_size)
{
    const float* x       = (const float*)d_in[0];
    const float* offsets = (const float*)d_in[1];
    const float* ef_w    = (const float*)d_in[2];
    const float* ef_b    = (const float*)d_in[3];
    const float* hm1_w   = (const float*)d_in[4];
    const float* hm1_b   = (const float*)d_in[5];
    const float* hm2_w   = (const float*)d_in[6];
    const float* hm2_b   = (const float*)d_in[7];
    const float* merge_w = (const float*)d_in[8];
    const float* merge_b = (const float*)d_in[9];
    const float* gn_g    = (const float*)d_in[10];
    const float* gn_b    = (const float*)d_in[11];
    float* out = (float*)d_out;

    float *ef, *heat, *hacc, *merged, *stat;
    __nv_bfloat16 *efs_h, *efs_l, *out_h, *out_l, *xs_h, *xs_l, *w_h, *w_l;
    cudaGetSymbolAddress((void**)&ef,     g_ef);
    cudaGetSymbolAddress((void**)&efs_h,  g_efs_h);
    cudaGetSymbolAddress((void**)&efs_l,  g_efs_l);
    cudaGetSymbolAddress((void**)&out_h,  g_out_h);
    cudaGetSymbolAddress((void**)&out_l,  g_out_l);
    cudaGetSymbolAddress((void**)&xs_h,   g_xs_h);
    cudaGetSymbolAddress((void**)&xs_l,   g_xs_l);
    cudaGetSymbolAddress((void**)&w_h,    g_w_h);
    cudaGetSymbolAddress((void**)&w_l,    g_w_l);
    cudaGetSymbolAddress((void**)&heat,   g_heat);
    cudaGetSymbolAddress((void**)&hacc,   g_hacc);
    cudaGetSymbolAddress((void**)&merged, g_merged);
    cudaGetSymbolAddress((void**)&stat,   g_stat);

    cudaFuncSetAttribute(tc_gemm<1, false, 1>, cudaFuncAttributeMaxDynamicSharedMemorySize, GEMM_SMEM);
    cudaFuncSetAttribute(tc_gemm<1, false, 2>, cudaFuncAttributeMaxDynamicSharedMemorySize, GEMM_SMEM);
    cudaFuncSetAttribute(tc_gemm<2, false, 0>, cudaFuncAttributeMaxDynamicSharedMemorySize, GEMM_SMEM);

    // 0) split weights + x (transpose), zero heat accumulator
    split_w_kernel<<<(DEXP * C_ + 255) / 256, 256>>>(ef_w, w_h + WOFF_EF, w_l + WOFF_EF, DEXP * C_);
    split_w_kernel<<<(P_ * C_ * C_ + 255) / 256, 256>>>(hm1_w, w_h + WOFF_HM1, w_l + WOFF_HM1, P_ * C_ * C_);
    split_w_kernel<<<(C_ * DEXP + 255) / 256, 256>>>(merge_w, w_h + WOFF_MRG, w_l + WOFF_MRG, C_ * DEXP);
    {
        dim3 grid((HW_ + 31) / 32, C_ / 32, B_);
        split_x_kernel<<<grid, dim3(32, 8)>>>(x, xs_h, xs_l);
    }
    zero_kernel<<<(B_ * P_ * HW_ + 255) / 256, 256>>>(hacc, B_ * P_ * HW_);

    // 1) GEMM1: ef[b][i][d] = sum_c xT[b][i][c]*ef_w[d][c] + ef_b[d]
    //    M=HW, N=512, K=256; EPI=1 writes fp32 ef + split planes
    {
        dim3 grid(DEXP / GBN, (HW_ + GBM - 1) / GBM, B_);
        tc_gemm<1, false, 1><<<grid, 256, GEMM_SMEM>>>(
            xs_h, xs_l, C_, (long)HW_ * C_, 0,
            w_h + WOFF_EF, w_l + WOFF_EF, C_, 0, 0,
            ef, DEXP, (long)HW_ * DEXP, 0,
            ef_b, 0, 0,
            efs_h, efs_l, nullptr, nullptr,
            1, HW_, DEXP, C_);
    }

    // 2) GEMM2 + heat fusion: hacc[z][i] += sum_d relu(h)*hm2_w[p][d]
    //    M=HW, N=256, K=256, z=(b,p)
    {
        dim3 grid(C_ / GBN, (HW_ + GBM - 1) / GBM, B_ * P_);
        tc_gemm<1, false, 2><<<grid, 256, GEMM_SMEM>>>(
            efs_h, efs_l, DEXP, (long)HW_ * DEXP, (long)C_,
            w_h + WOFF_HM1, w_l + WOFF_HM1, C_, 0, (long)C_ * C_,
            nullptr, 0, 0, 0,
            hm1_b, 0, (long)C_,
            nullptr, nullptr, hm2_w, hacc,
            P_, HW_, C_, C_);
    }

    // 3) heat = exp(hacc + hm2_b)
    heat_exp_kernel<<<(B_ * P_ * HW_ + 255) / 256, 256>>>(hacc, hm2_b, heat);

    // 4) gather -> split outs
    {
        int warps = B_ * P_ * HW_;
        sample_kernel<<<(warps * 32 + 255) / 256, 256>>>(ef, heat, offsets, out_h, out_l);
    }

    // 5) GEMM3: merged[b][dout][i] = sum_d merge_w[dout][d]*outs[b][i][d] + merge_b[dout]
    //    M=256, N=HW, K=512
    {
        dim3 grid((HW_ + GBN - 1) / GBN, C_ / GBM, B_);
        tc_gemm<2, false, 0><<<grid, 256, GEMM_SMEM>>>(
            w_h + WOFF_MRG, w_l + WOFF_MRG, DEXP, 0, 0,
            out_h, out_l, DEXP, (long)HW_ * DEXP, 0,
            merged, HW_, (long)C_ * HW_, 0,
            merge_b, 0, 0,
            nullptr, nullptr, nullptr, nullptr,
            1, C_, HW_, DEXP);
    }

    // 6) GroupNorm + ReLU
    gn_stats<<<B_ * 32, 256>>>(merged, stat);
    {
        long total = (long)B_ * C_ * HW_;
        gn_norm<<<(int)((total + 255) / 256), 256>>>(merged, stat, gn_g, gn_b, out);
    }
}

// round 5
// speedup vs baseline: 2.2743x; 1.2145x over previous
#include <cuda_runtime.h>
#include <cuda_bf16.h>
#include <cstdint>
#include <math.h>

#define B_   2
#define C_   256
#define H_   100
#define W_   152
#define HW_  (H_*W_)
#define P_   2
#define KB_  5          // bins
#define DEXP (P_*C_)    // 512

// ---------------- scratch (static device memory; no allocation) -------------
__device__ float         g_ef   [(size_t)B_*HW_*DEXP];   // (B, HW, 512) fp32 for gather
__device__ __nv_bfloat16 g_efs_h[(size_t)B_*HW_*DEXP];   // ef split hi
__device__ __nv_bfloat16 g_efs_l[(size_t)B_*HW_*DEXP];   // ef split lo
__device__ __nv_bfloat16 g_out_h[(size_t)B_*HW_*DEXP];   // gather out split hi
__device__ __nv_bfloat16 g_out_l[(size_t)B_*HW_*DEXP];   // gather out split lo
__device__ __nv_bfloat16 g_xs_h [(size_t)B_*HW_*C_];     // x transposed+split hi
__device__ __nv_bfloat16 g_xs_l [(size_t)B_*HW_*C_];
#define WOFF_EF   0
#define WOFF_HM1  (DEXP*C_)                  // 131072
#define WOFF_MRG  (DEXP*C_ + P_*C_*C_)       // 262144
__device__ __nv_bfloat16 g_w_h  [DEXP*C_ + P_*C_*C_ + C_*DEXP];
__device__ __nv_bfloat16 g_w_l  [DEXP*C_ + P_*C_*C_ + C_*DEXP];
__device__ float g_heat [B_*P_*HW_];
__device__ float g_hacc [B_*P_*HW_];
__device__ float g_merged[(size_t)B_*C_*HW_];
__device__ float g_stat2[B_*32*2];           // (b,g) -> sum, sumsq (atomic)

// ======================= helpers =============================================
__device__ __forceinline__ uint32_t smem_u32(const void* p) {
    uint32_t a;
    asm("{ .reg .u64 t; cvta.to.shared.u64 t, %1; cvt.u32.u64 %0, t; }" : "=r"(a) : "l"(p));
    return a;
}
__device__ __forceinline__ void ldsm_x4(uint32_t* r, uint32_t a) {
    asm volatile("ldmatrix.sync.aligned.m8n8.x4.shared.b16 {%0,%1,%2,%3}, [%4];"
        : "=r"(r[0]), "=r"(r[1]), "=r"(r[2]), "=r"(r[3]) : "r"(a));
}
__device__ __forceinline__ void mma_bf16(float* d, const uint32_t* a, const uint32_t* b) {
    asm volatile("mma.sync.aligned.m16n8k16.row.col.f32.bf16.bf16.f32 "
        "{%0,%1,%2,%3}, {%4,%5,%6,%7}, {%8,%9}, {%0,%1,%2,%3};"
        : "+f"(d[0]), "+f"(d[1]), "+f"(d[2]), "+f"(d[3])
        : "r"(a[0]), "r"(a[1]), "r"(a[2]), "r"(a[3]), "r"(b[0]), "r"(b[1]));
}
__device__ __forceinline__ void cvt_split(float f, unsigned short& h, unsigned short& l) {
    __nv_bfloat16 hb = __float2bfloat16(f);
    __nv_bfloat16 lb = __float2bfloat16(f - __bfloat162float(hb));
    h = __bfloat16_as_ushort(hb);
    l = __bfloat16_as_ushort(lb);
}
__device__ __forceinline__ void cp_async16(uint32_t dst, const void* src, int src_bytes) {
    asm volatile("cp.async.cg.shared.global [%0], [%1], 16, %2;"
        :: "r"(dst), "l"(src), "r"(src_bytes) : "memory");
}
#define CP_COMMIT() asm volatile("cp.async.commit_group;" ::: "memory")
#define CP_WAIT(n)  asm volatile("cp.async.wait_group %0;" :: "n"(n) : "memory")

// ======================= bf16x3 mma.sync GEMM (pre-split operands) ===========
// D[M,N] = A[M,K] * B[N,K]^T; A,B given as bf16 hi/lo planes, K-major.
// EPI: 0/3 = fp32 C (+bias); 3 also atomically accumulates GN sums (GEMM3);
//      1 = fp32 C + bf16 hi/lo C planes (GEMM1);
//      2 = no C store; heat fusion: atomicAdd( sum_n relu(c+bias)*w2[n] ).
#define GBM 128
#define GBN 128
#define GBK 32
#define ROWB   80                  // smem row pitch (odd 16B stride -> LDSM conflict-free)
#define TILE_B (128*ROWB)          // 10240 B per plane tile
#define BUF_B  (4*TILE_B)          // Ah, Al, Bh, Bl
#define GEMM_SMEM (2*BUF_B)        // 81920 B double buffered

template<int BIAS_MODE, bool RELU, int EPI>
__global__ __launch_bounds__(256, 2)
void tc_gemm(const __nv_bfloat16* __restrict__ Ah, const __nv_bfloat16* __restrict__ Al,
             int lda, long sA1, long sA2,
             const __nv_bfloat16* __restrict__ Bh, const __nv_bfloat16* __restrict__ Bl,
             int ldb, long sB1, long sB2,
             float* __restrict__ Cm, int ldc, long sC1, long sC2,
             const float* __restrict__ bias, long sb1, long sb2,
             __nv_bfloat16* __restrict__ Ch, __nv_bfloat16* __restrict__ Cl,
             const float* __restrict__ w2, float* __restrict__ aux,
             int zdiv, int M, int N, int K)
{
    extern __shared__ char smem[];
    const uint32_t sbase = smem_u32(smem);
    const int tid = threadIdx.x;
    const int lane = tid & 31, wid = tid >> 5;

    const int z = blockIdx.z;
    const int z1 = z / zdiv, z2 = z % zdiv;
    Ah += z1 * sA1 + z2 * sA2;  Al += z1 * sA1 + z2 * sA2;
    Bh += z1 * sB1 + z2 * sB2;  Bl += z1 * sB1 + z2 * sB2;
    const float* bptr = bias + z1 * sb1 + z2 * sb2;

    const int m0 = blockIdx.y * GBM;
    const int n0 = blockIdx.x * GBN;

    const int wm = wid & 3;          // 4 warps over M
    const int wn = wid >> 2;         // 2 warps over N
    const int lane8 = lane & 7, sel = lane >> 3;

    float acc[2][8][4];
#pragma unroll
    for (int i = 0; i < 2; i++)
#pragma unroll
        for (int j = 0; j < 8; j++)
#pragma unroll
            for (int q = 0; q < 4; q++) acc[i][j][q] = 0.f;

    const int nk = K / GBK;

    auto LOADCP = [&](int kt) {
        const int k0 = kt * GBK;
        const uint32_t sb = sbase + (kt & 1) * BUF_B;
#pragma unroll
        for (int j = 0; j < 2; j++) {
            int lin = tid + j * 256;           // 0..511
            int row = lin >> 2, q = lin & 3;
            uint32_t off = (uint32_t)(row * ROWB + q * 16);
            int gm = m0 + row, gn = n0 + row;
            int szA = (gm < M) ? 16 : 0;
            int szB = (gn < N) ? 16 : 0;
            long ga = (long)(gm < M ? gm : M - 1) * lda + k0 + q * 8;
            long gb = (long)(gn < N ? gn : N - 1) * ldb + k0 + q * 8;
            cp_async16(sb + off,              Ah + ga, szA);
            cp_async16(sb + TILE_B + off,     Al + ga, szA);
            cp_async16(sb + 2 * TILE_B + off, Bh + gb, szB);
            cp_async16(sb + 3 * TILE_B + off, Bl + gb, szB);
        }
    };

    auto COMPUTE = [&](int bsel) {
        const uint32_t ah_b = sbase + bsel * BUF_B;
        const uint32_t al_b = ah_b + TILE_B;
        const uint32_t bh_b = ah_b + 2 * TILE_B;
        const uint32_t bl_b = ah_b + 3 * TILE_B;
#pragma unroll
        for (int ks = 0; ks < 2; ks++) {
            const int kb = ks * 16;
            uint32_t ah[2][4], al[2][4];
#pragma unroll
            for (int mf = 0; mf < 2; mf++) {
                int row = wm * 32 + mf * 16 + lane8 + (sel & 1) * 8;
                int kc  = kb + (sel & 2) * 4;
                uint32_t off = (uint32_t)(row * ROWB + kc * 2);
                ldsm_x4(ah[mf], ah_b + off);
                ldsm_x4(al[mf], al_b + off);
            }
#pragma unroll
            for (int nf2 = 0; nf2 < 4; nf2++) {
                int nrow = wn * 64 + nf2 * 16 + lane8 + (sel & 2) * 4;
                int kc   = kb + (sel & 1) * 8;
                uint32_t off = (uint32_t)(nrow * ROWB + kc * 2);
                uint32_t bh4[4], bl4[4];
                ldsm_x4(bh4, bh_b + off);
                ldsm_x4(bl4, bl_b + off);
                // pass-major: same-accumulator MMAs are 4 apart (hide latency)
#pragma unroll
                for (int half = 0; half < 2; half++)
#pragma unroll
                    for (int mf = 0; mf < 2; mf++)
                        mma_bf16(acc[mf][nf2 * 2 + half], ah[mf], bh4 + half * 2);
#pragma unroll
                for (int half = 0; half < 2; half++)
#pragma unroll
                    for (int mf = 0; mf < 2; mf++)
                        mma_bf16(acc[mf][nf2 * 2 + half], ah[mf], bl4 + half * 2);
#pragma unroll
                for (int half = 0; half < 2; half++)
#pragma unroll
                    for (int mf = 0; mf < 2; mf++)
                        mma_bf16(acc[mf][nf2 * 2 + half], al[mf], bh4 + half * 2);
            }
        }
    };

    LOADCP(0); CP_COMMIT();
    for (int kt = 0; kt < nk; kt++) {
        if (kt + 1 < nk) { LOADCP(kt + 1); CP_COMMIT(); CP_WAIT(1); }
        else             { CP_WAIT(0); }
        __syncthreads();
        COMPUTE(kt & 1);
        __syncthreads();
    }

    // ---- epilogue ----
    const int g = lane >> 2, t = lane & 3;

    if (EPI == 2) {
        // heat fusion: s[row] = sum_n relu(c + bias[n]) * w2[n], atomicAdd per row
        const float* w2p = w2 + z2 * C_;
        float s[2][2] = {{0.f, 0.f}, {0.f, 0.f}};
#pragma unroll
        for (int nf = 0; nf < 8; nf++) {
            int gn = n0 + wn * 64 + nf * 8 + 2 * t;
            float b0 = bptr[gn], b1 = bptr[gn + 1];
            float w0 = w2p[gn],  w1 = w2p[gn + 1];
#pragma unroll
            for (int mf = 0; mf < 2; mf++)
#pragma unroll
                for (int rr = 0; rr < 2; rr++) {
                    float v0 = fmaxf(acc[mf][nf][rr * 2 + 0] + b0, 0.f);
                    float v1 = fmaxf(acc[mf][nf][rr * 2 + 1] + b1, 0.f);
                    s[mf][rr] += v0 * w0 + v1 * w1;
                }
        }
#pragma unroll
        for (int mf = 0; mf < 2; mf++)
#pragma unroll
            for (int rr = 0; rr < 2; rr++) {
                s[mf][rr] += __shfl_xor_sync(0xffffffffu, s[mf][rr], 1);
                s[mf][rr] += __shfl_xor_sync(0xffffffffu, s[mf][rr], 2);
            }
        if (t == 0) {
            float* hz = aux + (long)z * HW_;
#pragma unroll
            for (int mf = 0; mf < 2; mf++)
#pragma unroll
                for (int rr = 0; rr < 2; rr++) {
                    int gm = m0 + wm * 32 + mf * 16 + rr * 8 + g;
                    if (gm < M) atomicAdd(hz + gm, s[mf][rr]);
                }
        }
        return;
    }

    Cm += z1 * sC1 + z2 * sC2;
    if (EPI == 1) { Ch += z1 * sC1 + z2 * sC2; Cl += z1 * sC1 + z2 * sC2; }

    float gs[2][2]  = {{0.f, 0.f}, {0.f, 0.f}};   // GN sums (EPI==3)
    float gs2[2][2] = {{0.f, 0.f}, {0.f, 0.f}};

#pragma unroll
    for (int mf = 0; mf < 2; mf++) {
#pragma unroll
        for (int nf = 0; nf < 8; nf++) {
            const float* d = acc[mf][nf];
            int gm0 = m0 + wm * 32 + mf * 16 + g;
            int gn  = n0 + wn * 64 + nf * 8 + 2 * t;
            if (gn >= N) continue;
            float bc0 = 0.f, bc1 = 0.f;
            if (BIAS_MODE == 1) { bc0 = bptr[gn]; bc1 = bptr[gn + 1]; }
#pragma unroll
            for (int rr = 0; rr < 2; rr++) {
                int gm = gm0 + rr * 8;
                if (gm >= M) continue;
                float v0 = d[rr * 2 + 0], v1 = d[rr * 2 + 1];
                if (BIAS_MODE == 1) { v0 += bc0; v1 += bc1; }
                else { float br = bptr[gm]; v0 += br; v1 += br; }
                if (RELU) { v0 = fmaxf(v0, 0.f); v1 = fmaxf(v1, 0.f); }
                long idx = (long)gm * ldc + gn;
                *reinterpret_cast<float2*>(Cm + idx) = make_float2(v0, v1);
                if (EPI == 1) {
                    unsigned short h0, l0, h1, l1;
                    cvt_split(v0, h0, l0); cvt_split(v1, h1, l1);
                    *reinterpret_cast<uint32_t*>(Ch + idx) =
                        (uint32_t)h0 | ((uint32_t)h1 << 16);
                    *reinterpret_cast<uint32_t*>(Cl + idx) =
                        (uint32_t)l0 | ((uint32_t)l1 << 16);
                }
                if (EPI == 3) {
                    gs[mf][rr]  += v0 + v1;
                    gs2[mf][rr] += v0 * v0 + v1 * v1;
                }
            }
        }
    }

    if (EPI == 3) {
        // each (mf,rr) row-block of a warp lies within one GN group (8 channels)
#pragma unroll
        for (int mf = 0; mf < 2; mf++)
#pragma unroll
            for (int rr = 0; rr < 2; rr++) {
#pragma unroll
                for (int o = 16; o; o >>= 1) {
                    gs[mf][rr]  += __shfl_xor_sync(0xffffffffu, gs[mf][rr],  o);
                    gs2[mf][rr] += __shfl_xor_sync(0xffffffffu, gs2[mf][rr], o);
                }
                if (lane == 0) {
                    int gidx = (m0 + wm * 32 + mf * 16 + rr * 8) >> 3;   // 0..31
                    atomicAdd(aux + (z1 * 32 + gidx) * 2 + 0, gs[mf][rr]);
                    atomicAdd(aux + (z1 * 32 + gidx) * 2 + 1, gs2[mf][rr]);
                }
            }
    }
}

// ---------------- splitters --------------------------------------------------
__global__ void split_w_kernel(const float* __restrict__ w,
                               __nv_bfloat16* __restrict__ h,
                               __nv_bfloat16* __restrict__ l, int n)
{
    int i = blockIdx.x * 256 + threadIdx.x;
    if (i >= n) return;
    unsigned short hh, ll;
    cvt_split(w[i], hh, ll);
    h[i] = __ushort_as_bfloat16(hh);
    l[i] = __ushort_as_bfloat16(ll);
}

// transpose x (B,C,HW) -> split planes (B,HW,C)
__global__ void split_x_kernel(const float* __restrict__ x,
                               __nv_bfloat16* __restrict__ xh,
                               __nv_bfloat16* __restrict__ xl)
{
    __shared__ float tile[32][33];
    int b = blockIdx.z;
    int hw0 = blockIdx.x * 32, c0 = blockIdx.y * 32;
    const float* xb = x + (long)b * C_ * HW_;
    int tx = threadIdx.x, ty = threadIdx.y;   // 32 x 8
#pragma unroll
    for (int i = 0; i < 32; i += 8) {
        int c = c0 + ty + i, hw = hw0 + tx;
        tile[ty + i][tx] = (hw < HW_) ? xb[(long)c * HW_ + hw] : 0.f;
    }
    __syncthreads();
#pragma unroll
    for (int i = 0; i < 32; i += 8) {
        int hw = hw0 + ty + i, c = c0 + tx;
        if (hw < HW_) {
            unsigned short h, l;
            cvt_split(tile[tx][ty + i], h, l);
            long idx = (long)b * HW_ * C_ + (long)hw * C_ + c;
            xh[idx] = __ushort_as_bfloat16(h);
            xl[idx] = __ushort_as_bfloat16(l);
        }
    }
}

__global__ void zero2_kernel(float* __restrict__ p, int n,
                             float* __restrict__ q, int m)
{
    int i = blockIdx.x * 256 + threadIdx.x;
    if (i < n) p[i] = 0.f;
    if (i < m) q[i] = 0.f;
}

__global__ void heat_exp_kernel(const float* __restrict__ hacc,
                                const float* __restrict__ hm2_b,
                                float* __restrict__ heat)
{
    int i = blockIdx.x * 256 + threadIdx.x;
    if (i >= B_ * P_ * HW_) return;
    int p = (i / HW_) % P_;
    heat[i] = expf(hacc[i] + hm2_b[p]);
}

// ---------------- deformable bilinear gather (float4 path) -------------------
__global__ void sample_kernel(const float* __restrict__ ef,    // (B, HW, 512) fp32
                              const float* __restrict__ heat,  // (B*P, HW)
                              const float* __restrict__ offs,  // (B, P*KB*2, HW)
                              __nv_bfloat16* __restrict__ oh,  // split hi (B,HW,512)
                              __nv_bfloat16* __restrict__ ol)  // split lo
{
    int gw = (blockIdx.x * blockDim.x + threadIdx.x) >> 5;
    int lane = threadIdx.x & 31;
    if (gw >= B_ * P_ * HW_) return;
    int i  = gw % HW_;
    int bp = gw / HW_;
    int p  = bp % P_;
    int b  = bp / P_;
    int y = i / W_, x = i % W_;

    float4 n0 = make_float4(0.f, 0.f, 0.f, 0.f);
    float4 n1 = make_float4(0.f, 0.f, 0.f, 0.f);
    float den = 0.f;

    // lane handles channels [lane*8, lane*8+8)
    const float4* efb4  = reinterpret_cast<const float4*>(ef + ((long)b * HW_) * DEXP + p * C_)
                        + lane * 2;
    const float* heatb = heat + (long)bp * HW_;
    const float* offb  = offs + ((long)b * (P_ * KB_ * 2) + p * KB_ * 2) * HW_;

#pragma unroll
    for (int k = 0; k < KB_; k++) {
        float ys = (float)y + offb[(k * 2 + 0) * HW_ + i];
        float xs = (float)x + offb[(k * 2 + 1) * HW_ + i];
        float y0f = floorf(ys), x0f = floorf(xs);
#pragma unroll
        for (int c4 = 0; c4 < 4; c4++) {
            float yi = y0f + (float)(c4 >> 1);
            float xi = x0f + (float)(c4 & 1);
            if (yi < 0.f || yi > (float)(H_ - 1) || xi < 0.f || xi > (float)(W_ - 1))
                continue;
            float w = (1.f - fabsf(ys - yi)) * (1.f - fabsf(xs - xi));
            int src = (int)yi * W_ + (int)xi;
            float wh = w * heatb[src];
            den += wh;
            const float4* e4 = efb4 + (long)src * (DEXP / 4);
            float4 a = e4[0], c = e4[1];
            n0.x += wh * a.x; n0.y += wh * a.y; n0.z += wh * a.z; n0.w += wh * a.w;
            n1.x += wh * c.x; n1.y += wh * c.y; n1.z += wh * c.z; n1.w += wh * c.w;
        }
    }
    float inv = 1.f / (den + 1e-6f);
    float v[8] = {n0.x * inv, n0.y * inv, n0.z * inv, n0.w * inv,
                  n1.x * inv, n1.y * inv, n1.z * inv, n1.w * inv};
    unsigned short hh[8], ll[8];
#pragma unroll
    for (int j = 0; j < 8; j++) cvt_split(v[j], hh[j], ll[j]);
    uint4 ph, pl;
    ph.x = (uint32_t)hh[0] | ((uint32_t)hh[1] << 16);
    ph.y = (uint32_t)hh[2] | ((uint32_t)hh[3] << 16);
    ph.z = (uint32_t)hh[4] | ((uint32_t)hh[5] << 16);
    ph.w = (uint32_t)hh[6] | ((uint32_t)hh[7] << 16);
    pl.x = (uint32_t)ll[0] | ((uint32_t)ll[1] << 16);
    pl.y = (uint32_t)ll[2] | ((uint32_t)ll[3] << 16);
    pl.z = (uint32_t)ll[4] | ((uint32_t)ll[5] << 16);
    pl.w = (uint32_t)ll[6] | ((uint32_t)ll[7] << 16);
    long obase = ((long)b * HW_ + i) * DEXP + p * C_ + lane * 8;
    *reinterpret_cast<uint4*>(oh + obase) = ph;
    *reinterpret_cast<uint4*>(ol + obase) = pl;
}

// ---------------- GroupNorm finalize (stats precomputed atomically) ----------
__global__ void gn_norm(const float* __restrict__ merged,
                        const float* __restrict__ stat2,
                        const float* __restrict__ gn_g,
                        const float* __restrict__ gn_b,
                        float* __restrict__ out)
{
    long idx = (long)blockIdx.x * 256 + threadIdx.x;
    const long total = (long)B_ * C_ * HW_;
    if (idx >= total) return;
    int c = (int)((idx / HW_) % C_);
    int b = (int)(idx / ((long)C_ * HW_));
    int g = c >> 3;
    const float n = 8.f * HW_;
    float s  = stat2[(b * 32 + g) * 2 + 0];
    float s2 = stat2[(b * 32 + g) * 2 + 1];
    float mu   = s / n;
    float var  = s2 / n - mu * mu;
    float rstd = rsqrtf(var + 1e-5f);
    float v = (merged[idx] - mu) * rstd * gn_g[c] + gn_b[c];
    out[idx] = fmaxf(v, 0.f);
}

// ---------------- launch ------------------------------------------------------
extern "C" void kernel_launch(void* const* d_in, const int* in_sizes, int n_in,
                              void* d_out, int out_size)
{
    const float* x       = (const float*)d_in[0];
    const float* offsets = (const float*)d_in[1];
    const float* ef_w    = (const float*)d_in[2];
    const float* ef_b    = (const float*)d_in[3];
    const float* hm1_w   = (const float*)d_in[4];
    const float* hm1_b   = (const float*)d_in[5];
    const float* hm2_w   = (const float*)d_in[6];
    const float* hm2_b   = (const float*)d_in[7];
    const float* merge_w = (const float*)d_in[8];
    const float* merge_b = (const float*)d_in[9];
    const float* gn_g    = (const float*)d_in[10];
    const float* gn_b    = (const float*)d_in[11];
    float* out = (float*)d_out;

    float *ef, *heat, *hacc, *merged, *stat2;
    __nv_bfloat16 *efs_h, *efs_l, *out_h, *out_l, *xs_h, *xs_l, *w_h, *w_l;
    cudaGetSymbolAddress((void**)&ef,     g_ef);
    cudaGetSymbolAddress((void**)&efs_h,  g_efs_h);
    cudaGetSymbolAddress((void**)&efs_l,  g_efs_l);
    cudaGetSymbolAddress((void**)&out_h,  g_out_h);
    cudaGetSymbolAddress((void**)&out_l,  g_out_l);
    cudaGetSymbolAddress((void**)&xs_h,   g_xs_h);
    cudaGetSymbolAddress((void**)&xs_l,   g_xs_l);
    cudaGetSymbolAddress((void**)&w_h,    g_w_h);
    cudaGetSymbolAddress((void**)&w_l,    g_w_l);
    cudaGetSymbolAddress((void**)&heat,   g_heat);
    cudaGetSymbolAddress((void**)&hacc,   g_hacc);
    cudaGetSymbolAddress((void**)&merged, g_merged);
    cudaGetSymbolAddress((void**)&stat2,  g_stat2);

    cudaFuncSetAttribute(tc_gemm<1, false, 1>, cudaFuncAttributeMaxDynamicSharedMemorySize, GEMM_SMEM);
    cudaFuncSetAttribute(tc_gemm<1, false, 2>, cudaFuncAttributeMaxDynamicSharedMemorySize, GEMM_SMEM);
    cudaFuncSetAttribute(tc_gemm<2, false, 3>, cudaFuncAttributeMaxDynamicSharedMemorySize, GEMM_SMEM);

    // 0) split weights + x (transpose), zero accumulators
    split_w_kernel<<<(DEXP * C_ + 255) / 256, 256>>>(ef_w, w_h + WOFF_EF, w_l + WOFF_EF, DEXP * C_);
    split_w_kernel<<<(P_ * C_ * C_ + 255) / 256, 256>>>(hm1_w, w_h + WOFF_HM1, w_l + WOFF_HM1, P_ * C_ * C_);
    split_w_kernel<<<(C_ * DEXP + 255) / 256, 256>>>(merge_w, w_h + WOFF_MRG, w_l + WOFF_MRG, C_ * DEXP);
    {
        dim3 grid((HW_ + 31) / 32, C_ / 32, B_);
        split_x_kernel<<<grid, dim3(32, 8)>>>(x, xs_h, xs_l);
    }
    zero2_kernel<<<(B_ * P_ * HW_ + 255) / 256, 256>>>(hacc, B_ * P_ * HW_, stat2, B_ * 32 * 2);

    // 1) GEMM1: ef[b][i][d] = sum_c xT[b][i][c]*ef_w[d][c] + ef_b[d]
    //    M=HW, N=512, K=256; EPI=1 writes fp32 ef + split planes
    {
        dim3 grid(DEXP / GBN, (HW_ + GBM - 1) / GBM, B_);
        tc_gemm<1, false, 1><<<grid, 256, GEMM_SMEM>>>(
            xs_h, xs_l, C_, (long)HW_ * C_, 0,
            w_h + WOFF_EF, w_l + WOFF_EF, C_, 0, 0,
            ef, DEXP, (long)HW_ * DEXP, 0,
            ef_b, 0, 0,
            efs_h, efs_l, nullptr, nullptr,
            1, HW_, DEXP, C_);
    }

    // 2) GEMM2 + heat fusion: hacc[z][i] += sum_d relu(h)*hm2_w[p][d]
    //    M=HW, N=256, K=256, z=(b,p)
    {
        dim3 grid(C_ / GBN, (HW_ + GBM - 1) / GBM, B_ * P_);
        tc_gemm<1, false, 2><<<grid, 256, GEMM_SMEM>>>(
            efs_h, efs_l, DEXP, (long)HW_ * DEXP, (long)C_,
            w_h + WOFF_HM1, w_l + WOFF_HM1, C_, 0, (long)C_ * C_,
            nullptr, 0, 0, 0,
            hm1_b, 0, (long)C_,
            nullptr, nullptr, hm2_w, hacc,
            P_, HW_, C_, C_);
    }

    // 3) heat = exp(hacc + hm2_b)
    heat_exp_kernel<<<(B_ * P_ * HW_ + 255) / 256, 256>>>(hacc, hm2_b, heat);

    // 4) gather -> split outs
    {
        int warps = B_ * P_ * HW_;
        sample_kernel<<<(warps * 32 + 255) / 256, 256>>>(ef, heat, offsets, out_h, out_l);
    }

    // 5) GEMM3 + GN stats: merged[b][c][i] = sum_d merge_w[c][d]*outs[b][i][d] + merge_b[c]
    //    M=256, N=HW, K=512; EPI=3 accumulates GN sums into stat2
    {
        dim3 grid((HW_ + GBN - 1) / GBN, C_ / GBM, B_);
        tc_gemm<2, false, 3><<<grid, 256, GEMM_SMEM>>>(
            w_h + WOFF_MRG, w_l + WOFF_MRG, DEXP, 0, 0,
            out_h, out_l, DEXP, (long)HW_ * DEXP, 0,
            merged, HW_, (long)C_ * HW_, 0,
            merge_b, 0, 0,
            nullptr, nullptr, nullptr, stat2,
            1, C_, HW_, DEXP);
    }

    // 6) GroupNorm finalize + ReLU
    {
        long total = (long)B_ * C_ * HW_;
        gn_norm<<<(int)((total + 255) / 256), 256>>>(merged, stat2, gn_g, gn_b, out);
    }
}

// round 6
// speedup vs baseline: 2.8819x; 1.2672x over previous
#include <cuda_runtime.h>
#include <cuda_fp16.h>
#include <cstdint>
#include <math.h>

#define B_   2
#define C_   256
#define H_   100
#define W_   152
#define HW_  (H_*W_)
#define P_   2
#define KB_  5          // bins
#define DEXP (P_*C_)    // 512

// ---------------- scratch (static device memory; no allocation) -------------
__device__ float    g_ef   [(size_t)B_*HW_*DEXP];   // (B, HW, 512) fp32 for gather
__device__ __half   g_efs_h[(size_t)B_*HW_*DEXP];   // ef fp16 (GEMM2 A operand)
__device__ __half   g_out_h[(size_t)B_*HW_*DEXP];   // gather out split hi
__device__ __half   g_out_l[(size_t)B_*HW_*DEXP];   // gather out split lo
__device__ __half   g_xs_h [(size_t)B_*HW_*C_];     // x transposed, fp16 (GEMM1 A)
#define WOFF_EF   0
#define WOFF_HM1  (DEXP*C_)                  // 131072
__device__ __half   g_w_h  [DEXP*C_ + P_*C_*C_];    // ef_w, hm1_w hi planes (B operands)
__device__ __half   g_w_l  [DEXP*C_ + P_*C_*C_];    // lo planes
__device__ __half   g_mw_h [C_*DEXP];               // merge_w fp16 (GEMM3 A)
__device__ float g_heat [B_*P_*HW_];
__device__ float g_hacc [B_*P_*HW_];
__device__ float g_merged[(size_t)B_*C_*HW_];
__device__ float g_stat2[B_*32*2];           // (b,g) -> sum, sumsq (atomic)

// ======================= helpers =============================================
__device__ __forceinline__ uint32_t smem_u32(const void* p) {
    uint32_t a;
    asm("{ .reg .u64 t; cvta.to.shared.u64 t, %1; cvt.u32.u64 %0, t; }" : "=r"(a) : "l"(p));
    return a;
}
__device__ __forceinline__ void ldsm_x4(uint32_t* r, uint32_t a) {
    asm volatile("ldmatrix.sync.aligned.m8n8.x4.shared.b16 {%0,%1,%2,%3}, [%4];"
        : "=r"(r[0]), "=r"(r[1]), "=r"(r[2]), "=r"(r[3]) : "r"(a));
}
__device__ __forceinline__ void mma_f16(float* d, const uint32_t* a, const uint32_t* b) {
    asm volatile("mma.sync.aligned.m16n8k16.row.col.f32.f16.f16.f32 "
        "{%0,%1,%2,%3}, {%4,%5,%6,%7}, {%8,%9}, {%0,%1,%2,%3};"
        : "+f"(d[0]), "+f"(d[1]), "+f"(d[2]), "+f"(d[3])
        : "r"(a[0]), "r"(a[1]), "r"(a[2]), "r"(a[3]), "r"(b[0]), "r"(b[1]));
}
__device__ __forceinline__ void cvt_split_f16(float f, unsigned short& h, unsigned short& l) {
    __half hb = __float2half_rn(f);
    __half lb = __float2half_rn(f - __half2float(hb));
    h = __half_as_ushort(hb);
    l = __half_as_ushort(lb);
}
__device__ __forceinline__ void cp_async16(uint32_t dst, const void* src, int src_bytes) {
    asm volatile("cp.async.cg.shared.global [%0], [%1], 16, %2;"
        :: "r"(dst), "l"(src), "r"(src_bytes) : "memory");
}
#define CP_COMMIT() asm volatile("cp.async.commit_group;" ::: "memory")
#define CP_WAIT(n)  asm volatile("cp.async.wait_group %0;" :: "n"(n) : "memory")

// ================= fp16 A-single/B-split 2-pass mma.sync GEMM ================
// D[M,N] = A[M,K] * B[N,K]^T;  A plain fp16 (1 plane), B split hi/lo fp16.
// EPI: 0/3 = fp32 C (+bias); 3 adds atomic GN sums (GEMM3);
//      1 = fp32 C + fp16 hi C plane (GEMM1);
//      2 = no C store; heat fusion: atomicAdd( sum_n relu(c+bias)*w2[n] ).
#define GBM 128
#define GBN 128
#define GBK 32
#define ROWB   80                  // smem row pitch (odd 16B stride -> LDSM conflict-free)
#define TILE_B (128*ROWB)          // 10240 B per plane tile
#define BUF_B  (3*TILE_B)          // Ah, Bh, Bl
#define GEMM_SMEM (2*BUF_B)        // 61440 B double buffered

template<int BIAS_MODE, int EPI>
__global__ __launch_bounds__(256, 2)
void tc_gemm(const __half* __restrict__ Ahp, int lda, long sA1, long sA2,
             const __half* __restrict__ Bhp, const __half* __restrict__ Blp,
             int ldb, long sB1, long sB2,
             float* __restrict__ Cm, int ldc, long sC1, long sC2,
             const float* __restrict__ bias, long sb1, long sb2,
             __half* __restrict__ Ch,
             const float* __restrict__ w2, float* __restrict__ aux,
             int zdiv, int M, int N, int K)
{
    extern __shared__ char smem[];
    const uint32_t sbase = smem_u32(smem);
    const int tid = threadIdx.x;
    const int lane = tid & 31, wid = tid >> 5;

    const int z = blockIdx.z;
    const int z1 = z / zdiv, z2 = z % zdiv;
    Ahp += z1 * sA1 + z2 * sA2;
    Bhp += z1 * sB1 + z2 * sB2;  Blp += z1 * sB1 + z2 * sB2;
    const float* bptr = bias + z1 * sb1 + z2 * sb2;

    const int m0 = blockIdx.y * GBM;
    const int n0 = blockIdx.x * GBN;

    const int wm = wid & 3;          // 4 warps over M
    const int wn = wid >> 2;         // 2 warps over N
    const int lane8 = lane & 7, sel = lane >> 3;

    float acc[2][8][4];
#pragma unroll
    for (int i = 0; i < 2; i++)
#pragma unroll
        for (int j = 0; j < 8; j++)
#pragma unroll
            for (int q = 0; q < 4; q++) acc[i][j][q] = 0.f;

    const int nk = K / GBK;

    auto LOADCP = [&](int kt) {
        const int k0 = kt * GBK;
        const uint32_t sb = sbase + (kt & 1) * BUF_B;
#pragma unroll
        for (int j = 0; j < 2; j++) {
            int lin = tid + j * 256;           // 0..511
            int row = lin >> 2, q = lin & 3;
            uint32_t off = (uint32_t)(row * ROWB + q * 16);
            int gm = m0 + row, gn = n0 + row;
            int szA = (gm < M) ? 16 : 0;
            int szB = (gn < N) ? 16 : 0;
            long ga = (long)(gm < M ? gm : M - 1) * lda + k0 + q * 8;
            long gb = (long)(gn < N ? gn : N - 1) * ldb + k0 + q * 8;
            cp_async16(sb + off,              Ahp + ga, szA);
            cp_async16(sb + TILE_B + off,     Bhp + gb, szB);
            cp_async16(sb + 2 * TILE_B + off, Blp + gb, szB);
        }
    };

    auto COMPUTE = [&](int bsel) {
        const uint32_t ah_b = sbase + bsel * BUF_B;
        const uint32_t bh_b = ah_b + TILE_B;
        const uint32_t bl_b = ah_b + 2 * TILE_B;
#pragma unroll
        for (int ks = 0; ks < 2; ks++) {
            const int kb = ks * 16;
            uint32_t ah[2][4];
#pragma unroll
            for (int mf = 0; mf < 2; mf++) {
                int row = wm * 32 + mf * 16 + lane8 + (sel & 1) * 8;
                int kc  = kb + (sel & 2) * 4;
                ldsm_x4(ah[mf], ah_b + (uint32_t)(row * ROWB + kc * 2));
            }
#pragma unroll
            for (int nf2 = 0; nf2 < 4; nf2++) {
                int nrow = wn * 64 + nf2 * 16 + lane8 + (sel & 2) * 4;
                int kc   = kb + (sel & 1) * 8;
                uint32_t off = (uint32_t)(nrow * ROWB + kc * 2);
                uint32_t bh4[4], bl4[4];
                ldsm_x4(bh4, bh_b + off);
                ldsm_x4(bl4, bl_b + off);
                // pass-major: same-accumulator MMAs are 4 apart
#pragma unroll
                for (int half = 0; half < 2; half++)
#pragma unroll
                    for (int mf = 0; mf < 2; mf++)
                        mma_f16(acc[mf][nf2 * 2 + half], ah[mf], bh4 + half * 2);
#pragma unroll
                for (int half = 0; half < 2; half++)
#pragma unroll
                    for (int mf = 0; mf < 2; mf++)
                        mma_f16(acc[mf][nf2 * 2 + half], ah[mf], bl4 + half * 2);
            }
        }
    };

    LOADCP(0); CP_COMMIT();
    for (int kt = 0; kt < nk; kt++) {
        if (kt + 1 < nk) { LOADCP(kt + 1); CP_COMMIT(); CP_WAIT(1); }
        else             { CP_WAIT(0); }
        __syncthreads();
        COMPUTE(kt & 1);
        __syncthreads();
    }

    // ---- epilogue ----
    const int g = lane >> 2, t = lane & 3;

    if (EPI == 2) {
        const float* w2p = w2 + z2 * C_;
        float s[2][2] = {{0.f, 0.f}, {0.f, 0.f}};
#pragma unroll
        for (int nf = 0; nf < 8; nf++) {
            int gn = n0 + wn * 64 + nf * 8 + 2 * t;
            float b0 = bptr[gn], b1 = bptr[gn + 1];
            float w0 = w2p[gn],  w1 = w2p[gn + 1];
#pragma unroll
            for (int mf = 0; mf < 2; mf++)
#pragma unroll
                for (int rr = 0; rr < 2; rr++) {
                    float v0 = fmaxf(acc[mf][nf][rr * 2 + 0] + b0, 0.f);
                    float v1 = fmaxf(acc[mf][nf][rr * 2 + 1] + b1, 0.f);
                    s[mf][rr] += v0 * w0 + v1 * w1;
                }
        }
#pragma unroll
        for (int mf = 0; mf < 2; mf++)
#pragma unroll
            for (int rr = 0; rr < 2; rr++) {
                s[mf][rr] += __shfl_xor_sync(0xffffffffu, s[mf][rr], 1);
                s[mf][rr] += __shfl_xor_sync(0xffffffffu, s[mf][rr], 2);
            }
        if (t == 0) {
            float* hz = aux + (long)z * HW_;
#pragma unroll
            for (int mf = 0; mf < 2; mf++)
#pragma unroll
                for (int rr = 0; rr < 2; rr++) {
                    int gm = m0 + wm * 32 + mf * 16 + rr * 8 + g;
                    if (gm < M) atomicAdd(hz + gm, s[mf][rr]);
                }
        }
        return;
    }

    Cm += z1 * sC1 + z2 * sC2;
    if (EPI == 1) Ch += z1 * sC1 + z2 * sC2;

    float gs[2][2]  = {{0.f, 0.f}, {0.f, 0.f}};
    float gs2[2][2] = {{0.f, 0.f}, {0.f, 0.f}};

#pragma unroll
    for (int mf = 0; mf < 2; mf++) {
#pragma unroll
        for (int nf = 0; nf < 8; nf++) {
            const float* d = acc[mf][nf];
            int gm0 = m0 + wm * 32 + mf * 16 + g;
            int gn  = n0 + wn * 64 + nf * 8 + 2 * t;
            if (gn >= N) continue;
            float bc0 = 0.f, bc1 = 0.f;
            if (BIAS_MODE == 1) { bc0 = bptr[gn]; bc1 = bptr[gn + 1]; }
#pragma unroll
            for (int rr = 0; rr < 2; rr++) {
                int gm = gm0 + rr * 8;
                if (gm >= M) continue;
                float v0 = d[rr * 2 + 0], v1 = d[rr * 2 + 1];
                if (BIAS_MODE == 1) { v0 += bc0; v1 += bc1; }
                else { float br = bptr[gm]; v0 += br; v1 += br; }
                long idx = (long)gm * ldc + gn;
                *reinterpret_cast<float2*>(Cm + idx) = make_float2(v0, v1);
                if (EPI == 1) {
                    __half h0 = __float2half_rn(v0), h1 = __float2half_rn(v1);
                    *reinterpret_cast<uint32_t*>(Ch + idx) =
                        (uint32_t)__half_as_ushort(h0) | ((uint32_t)__half_as_ushort(h1) << 16);
                }
                if (EPI == 3) {
                    gs[mf][rr]  += v0 + v1;
                    gs2[mf][rr] += v0 * v0 + v1 * v1;
                }
            }
        }
    }

    if (EPI == 3) {
#pragma unroll
        for (int mf = 0; mf < 2; mf++)
#pragma unroll
            for (int rr = 0; rr < 2; rr++) {
#pragma unroll
                for (int o = 16; o; o >>= 1) {
                    gs[mf][rr]  += __shfl_xor_sync(0xffffffffu, gs[mf][rr],  o);
                    gs2[mf][rr] += __shfl_xor_sync(0xffffffffu, gs2[mf][rr], o);
                }
                if (lane == 0) {
                    int gidx = (m0 + wm * 32 + mf * 16 + rr * 8) >> 3;   // 0..31
                    atomicAdd(aux + (z1 * 32 + gidx) * 2 + 0, gs[mf][rr]);
                    atomicAdd(aux + (z1 * 32 + gidx) * 2 + 1, gs2[mf][rr]);
                }
            }
    }
}

// ---------------- prep: split all weights + zero accumulators ----------------
__global__ void prep_kernel(const float* __restrict__ ef_w,
                            const float* __restrict__ hm1_w,
                            const float* __restrict__ merge_w,
                            __half* __restrict__ w_h, __half* __restrict__ w_l,
                            __half* __restrict__ mw_h,
                            float* __restrict__ hacc, float* __restrict__ stat2)
{
    int i = blockIdx.x * 256 + threadIdx.x;
    if (i < DEXP * C_) {
        unsigned short h, l;
        cvt_split_f16(ef_w[i], h, l);
        w_h[WOFF_EF + i] = __ushort_as_half(h);
        w_l[WOFF_EF + i] = __ushort_as_half(l);
    }
    if (i < P_ * C_ * C_) {
        unsigned short h, l;
        cvt_split_f16(hm1_w[i], h, l);
        w_h[WOFF_HM1 + i] = __ushort_as_half(h);
        w_l[WOFF_HM1 + i] = __ushort_as_half(l);
    }
    if (i < C_ * DEXP) mw_h[i] = __float2half_rn(merge_w[i]);
    if (i < B_ * P_ * HW_) hacc[i] = 0.f;
    if (i < B_ * 32 * 2) stat2[i] = 0.f;
}

// -------- transpose x (B,C,HW) -> fp16 plane (B,HW,C), packed stores ---------
__global__ void split_x_kernel(const float* __restrict__ x, __half* __restrict__ xh)
{
    __shared__ float tile[32][33];
    int b = blockIdx.z;
    int hw0 = blockIdx.x * 32, c0 = blockIdx.y * 32;
    const float* xb = x + (long)b * C_ * HW_;
    int tx = threadIdx.x, ty = threadIdx.y;   // 32 x 8
#pragma unroll
    for (int i = 0; i < 32; i += 8) {
        int c = c0 + ty + i, hw = hw0 + tx;
        tile[ty + i][tx] = (hw < HW_) ? xb[(long)c * HW_ + hw] : 0.f;
    }
    __syncthreads();
    int tid = ty * 32 + tx;
    int cpair = tid & 15;          // 16 c-pairs
    int hwl0  = tid >> 4;          // 0..15
#pragma unroll
    for (int rep = 0; rep < 2; rep++) {
        int hwl = hwl0 + rep * 16;
        int hw = hw0 + hwl;
        if (hw < HW_) {
            __half h0 = __float2half_rn(tile[2 * cpair + 0][hwl]);
            __half h1 = __float2half_rn(tile[2 * cpair + 1][hwl]);
            long idx = (long)b * HW_ * C_ + (long)hw * C_ + c0 + 2 * cpair;
            *reinterpret_cast<uint32_t*>(xh + idx) =
                (uint32_t)__half_as_ushort(h0) | ((uint32_t)__half_as_ushort(h1) << 16);
        }
    }
}

__global__ void heat_exp_kernel(const float* __restrict__ hacc,
                                const float* __restrict__ hm2_b,
                                float* __restrict__ heat)
{
    int i = blockIdx.x * 256 + threadIdx.x;
    if (i >= B_ * P_ * HW_) return;
    int p = (i / HW_) % P_;
    heat[i] = expf(hacc[i] + hm2_b[p]);
}

// ---------------- deformable bilinear gather (float4 path) -------------------
__global__ void sample_kernel(const float* __restrict__ ef,    // (B, HW, 512) fp32
                              const float* __restrict__ heat,  // (B*P, HW)
                              const float* __restrict__ offs,  // (B, P*KB*2, HW)
                              __half* __restrict__ oh,         // split hi (B,HW,512)
                              __half* __restrict__ ol)         // split lo
{
    int gw = (blockIdx.x * blockDim.x + threadIdx.x) >> 5;
    int lane = threadIdx.x & 31;
    if (gw >= B_ * P_ * HW_) return;
    int i  = gw % HW_;
    int bp = gw / HW_;
    int p  = bp % P_;
    int b  = bp / P_;
    int y = i / W_, x = i % W_;

    float4 n0 = make_float4(0.f, 0.f, 0.f, 0.f);
    float4 n1 = make_float4(0.f, 0.f, 0.f, 0.f);
    float den = 0.f;

    const float4* efb4  = reinterpret_cast<const float4*>(ef + ((long)b * HW_) * DEXP + p * C_)
                        + lane * 2;
    const float* heatb = heat + (long)bp * HW_;
    const float* offb  = offs + ((long)b * (P_ * KB_ * 2) + p * KB_ * 2) * HW_;

#pragma unroll
    for (int k = 0; k < KB_; k++) {
        float ys = (float)y + offb[(k * 2 + 0) * HW_ + i];
        float xs = (float)x + offb[(k * 2 + 1) * HW_ + i];
        float y0f = floorf(ys), x0f = floorf(xs);
#pragma unroll
        for (int c4 = 0; c4 < 4; c4++) {
            float yi = y0f + (float)(c4 >> 1);
            float xi = x0f + (float)(c4 & 1);
            if (yi < 0.f || yi > (float)(H_ - 1) || xi < 0.f || xi > (float)(W_ - 1))
                continue;
            float w = (1.f - fabsf(ys - yi)) * (1.f - fabsf(xs - xi));
            int src = (int)yi * W_ + (int)xi;
            float wh = w * heatb[src];
            den += wh;
            const float4* e4 = efb4 + (long)src * (DEXP / 4);
            float4 a = e4[0], c = e4[1];
            n0.x += wh * a.x; n0.y += wh * a.y; n0.z += wh * a.z; n0.w += wh * a.w;
            n1.x += wh * c.x; n1.y += wh * c.y; n1.z += wh * c.z; n1.w += wh * c.w;
        }
    }
    float inv = 1.f / (den + 1e-6f);
    float v[8] = {n0.x * inv, n0.y * inv, n0.z * inv, n0.w * inv,
                  n1.x * inv, n1.y * inv, n1.z * inv, n1.w * inv};
    unsigned short hh[8], ll[8];
#pragma unroll
    for (int j = 0; j < 8; j++) cvt_split_f16(v[j], hh[j], ll[j]);
    uint4 ph, pl;
    ph.x = (uint32_t)hh[0] | ((uint32_t)hh[1] << 16);
    ph.y = (uint32_t)hh[2] | ((uint32_t)hh[3] << 16);
    ph.z = (uint32_t)hh[4] | ((uint32_t)hh[5] << 16);
    ph.w = (uint32_t)hh[6] | ((uint32_t)hh[7] << 16);
    pl.x = (uint32_t)ll[0] | ((uint32_t)ll[1] << 16);
    pl.y = (uint32_t)ll[2] | ((uint32_t)ll[3] << 16);
    pl.z = (uint32_t)ll[4] | ((uint32_t)ll[5] << 16);
    pl.w = (uint32_t)ll[6] | ((uint32_t)ll[7] << 16);
    long obase = ((long)b * HW_ + i) * DEXP + p * C_ + lane * 8;
    *reinterpret_cast<uint4*>(oh + obase) = ph;
    *reinterpret_cast<uint4*>(ol + obase) = pl;
}

// ---------------- GroupNorm finalize (float4, stats precomputed) -------------
__global__ void gn_norm(const float* __restrict__ merged,
                        const float* __restrict__ stat2,
                        const float* __restrict__ gn_g,
                        const float* __restrict__ gn_b,
                        float* __restrict__ out)
{
    long i4 = (long)blockIdx.x * 256 + threadIdx.x;
    const long total4 = (long)B_ * C_ * HW_ / 4;
    if (i4 >= total4) return;
    long idx = i4 * 4;
    int c = (int)((idx / HW_) % C_);
    int b = (int)(idx / ((long)C_ * HW_));
    int g = c >> 3;
    const float n = 8.f * HW_;
    float s  = stat2[(b * 32 + g) * 2 + 0];
    float s2 = stat2[(b * 32 + g) * 2 + 1];
    float mu   = s / n;
    float var  = s2 / n - mu * mu;
    float rstd = rsqrtf(var + 1e-5f);
    float sc = rstd * gn_g[c];
    float sh = gn_b[c] - mu * sc;
    float4 v = *reinterpret_cast<const float4*>(merged + idx);
    float4 r;
    r.x = fmaxf(v.x * sc + sh, 0.f);
    r.y = fmaxf(v.y * sc + sh, 0.f);
    r.z = fmaxf(v.z * sc + sh, 0.f);
    r.w = fmaxf(v.w * sc + sh, 0.f);
    *reinterpret_cast<float4*>(out + idx) = r;
}

// ---------------- launch ------------------------------------------------------
extern "C" void kernel_launch(void* const* d_in, const int* in_sizes, int n_in,
                              void* d_out, int out_size)
{
    const float* x       = (const float*)d_in[0];
    const float* offsets = (const float*)d_in[1];
    const float* ef_w    = (const float*)d_in[2];
    const float* ef_b    = (const float*)d_in[3];
    const float* hm1_w   = (const float*)d_in[4];
    const float* hm1_b   = (const float*)d_in[5];
    const float* hm2_w   = (const float*)d_in[6];
    const float* hm2_b   = (const float*)d_in[7];
    const float* merge_w = (const float*)d_in[8];
    const float* merge_b = (const float*)d_in[9];
    const float* gn_g    = (const float*)d_in[10];
    const float* gn_b    = (const float*)d_in[11];
    float* out = (float*)d_out;

    float *ef, *heat, *hacc, *merged, *stat2;
    __half *efs_h, *out_h, *out_l, *xs_h, *w_h, *w_l, *mw_h;
    cudaGetSymbolAddress((void**)&ef,     g_ef);
    cudaGetSymbolAddress((void**)&efs_h,  g_efs_h);
    cudaGetSymbolAddress((void**)&out_h,  g_out_h);
    cudaGetSymbolAddress((void**)&out_l,  g_out_l);
    cudaGetSymbolAddress((void**)&xs_h,   g_xs_h);
    cudaGetSymbolAddress((void**)&w_h,    g_w_h);
    cudaGetSymbolAddress((void**)&w_l,    g_w_l);
    cudaGetSymbolAddress((void**)&mw_h,   g_mw_h);
    cudaGetSymbolAddress((void**)&heat,   g_heat);
    cudaGetSymbolAddress((void**)&hacc,   g_hacc);
    cudaGetSymbolAddress((void**)&merged, g_merged);
    cudaGetSymbolAddress((void**)&stat2,  g_stat2);

    cudaFuncSetAttribute(tc_gemm<1, 1>, cudaFuncAttributeMaxDynamicSharedMemorySize, GEMM_SMEM);
    cudaFuncSetAttribute(tc_gemm<1, 2>, cudaFuncAttributeMaxDynamicSharedMemorySize, GEMM_SMEM);
    cudaFuncSetAttribute(tc_gemm<2, 3>, cudaFuncAttributeMaxDynamicSharedMemorySize, GEMM_SMEM);

    // 0) prep: weight splits + zeroing (one kernel); x transpose->fp16
    prep_kernel<<<(DEXP * C_ + 255) / 256, 256>>>(ef_w, hm1_w, merge_w,
                                                  w_h, w_l, mw_h, hacc, stat2);
    {
        dim3 grid((HW_ + 31) / 32, C_ / 32, B_);
        split_x_kernel<<<grid, dim3(32, 8)>>>(x, xs_h);
    }

    // 1) GEMM1: ef[b][i][d] = sum_c xT[b][i][c]*ef_w[d][c] + ef_b[d]
    //    M=HW, N=512, K=256; A = xs_h (fp16), B = ef_w split
    {
        dim3 grid(DEXP / GBN, (HW_ + GBM - 1) / GBM, B_);
        tc_gemm<1, 1><<<grid, 256, GEMM_SMEM>>>(
            xs_h, C_, (long)HW_ * C_, 0,
            w_h + WOFF_EF, w_l + WOFF_EF, C_, 0, 0,
            ef, DEXP, (long)HW_ * DEXP, 0,
            ef_b, 0, 0,
            efs_h, nullptr, nullptr,
            1, HW_, DEXP, C_);
    }

    // 2) GEMM2 + heat fusion: hacc[z][i] += sum_d relu(h)*hm2_w[p][d]
    //    M=HW, N=256, K=256, z=(b,p); A = efs_h slice, B = hm1_w split
    {
        dim3 grid(C_ / GBN, (HW_ + GBM - 1) / GBM, B_ * P_);
        tc_gemm<1, 2><<<grid, 256, GEMM_SMEM>>>(
            efs_h, DEXP, (long)HW_ * DEXP, (long)C_,
            w_h + WOFF_HM1, w_l + WOFF_HM1, C_, 0, (long)C_ * C_,
            nullptr, 0, 0, 0,
            hm1_b, 0, (long)C_,
            nullptr, hm2_w, hacc,
            P_, HW_, C_, C_);
    }

    // 3) heat = exp(hacc + hm2_b)
    heat_exp_kernel<<<(B_ * P_ * HW_ + 255) / 256, 256>>>(hacc, hm2_b, heat);

    // 4) gather -> fp16 split outs
    {
        int warps = B_ * P_ * HW_;
        sample_kernel<<<(warps * 32 + 255) / 256, 256>>>(ef, heat, offsets, out_h, out_l);
    }

    // 5) GEMM3 + GN stats: merged[b][c][i] = sum_d merge_w[c][d]*outs[b][i][d] + merge_b[c]
    //    M=256, N=HW, K=512; A = mw_h (fp16), B = outs split
    {
        dim3 grid((HW_ + GBN - 1) / GBN, C_ / GBM, B_);
        tc_gemm<2, 3><<<grid, 256, GEMM_SMEM>>>(
            mw_h, DEXP, 0, 0,
            out_h, out_l, DEXP, (long)HW_ * DEXP, 0,
            merged, HW_, (long)C_ * HW_, 0,
            merge_b, 0, 0,
            nullptr, nullptr, stat2,
            1, C_, HW_, DEXP);
    }

    // 6) GroupNorm finalize + ReLU
    {
        long total4 = (long)B_ * C_ * HW_ / 4;
        gn_norm<<<(int)((total4 + 255) / 256), 256>>>(merged, stat2, gn_g, gn_b, out);
    }
}